// round 1
// baseline (speedup 1.0000x reference)
#include <cuda_runtime.h>
#include <math.h>

#define NN 50000
#define EE 800000
#define ETOT (EE + NN)
#define GG 64

// ---------------- scratch (static device allocations) ----------------
__device__ float d_h[NN * 96];     // GEMM output (message source)
__device__ float d_o[NN * 96];     // aggregation target / next layer input
__device__ float d_as[NN * 4];
__device__ float d_ad[NN * 4];
__device__ float d_m[NN * 4];
__device__ float d_den[NN * 4];
__device__ float d_ex[ETOT * 4];
__device__ float d_gate[NN];
__device__ float d_ge[NN];
__device__ float d_gm[GG];
__device__ float d_gden[GG];
__device__ float d_pool[GG * 96];

__device__ __forceinline__ void atomicMaxF(float* a, float v) {
    if (v >= 0.f) atomicMax((int*)a, __float_as_int(v));
    else          atomicMin((unsigned int*)a, __float_as_uint(v));
}

// ---------------- GEMM + fused attention-alpha epilogue ----------------
// C[n,96] = A[n,K] @ W[K,96].  128 threads: thread (rp,cq) computes rows
// {rp, rp+32} x head cq (24 cols).  alpha_src/dst computed in-register.
__global__ void k_gemm_alpha(const float* __restrict__ A, const float* __restrict__ W,
                             const float* __restrict__ asrc, const float* __restrict__ adst,
                             float* __restrict__ H, float* __restrict__ AS, float* __restrict__ AD,
                             int n, int K) {
    __shared__ float As[64][33];
    __shared__ float Bs[32][96];
    int t = threadIdx.x;          // 128 threads
    int rp = t & 31, cq = t >> 5;
    int row0 = blockIdx.x * 64;
    float acc0[24], acc1[24];
#pragma unroll
    for (int j = 0; j < 24; j++) { acc0[j] = 0.f; acc1[j] = 0.f; }

    for (int k0 = 0; k0 < K; k0 += 32) {
        for (int i = t; i < 64 * 32; i += 128) {
            int rr = i >> 5, kk = i & 31;
            int row = row0 + rr;
            As[rr][kk] = (row < n) ? A[row * K + k0 + kk] : 0.f;
        }
        for (int i = t; i < 32 * 96; i += 128) {
            int kk = i / 96, cc = i - kk * 96;
            Bs[kk][cc] = W[(k0 + kk) * 96 + cc];
        }
        __syncthreads();
#pragma unroll
        for (int k = 0; k < 32; k++) {
            float a0 = As[rp][k], a1 = As[rp + 32][k];
#pragma unroll
            for (int j = 0; j < 24; j++) {
                float b = Bs[k][cq * 24 + j];
                acc0[j] = fmaf(a0, b, acc0[j]);
                acc1[j] = fmaf(a1, b, acc1[j]);
            }
        }
        __syncthreads();
    }

    float s0 = 0.f, dd0 = 0.f, s1 = 0.f, dd1 = 0.f;
#pragma unroll
    for (int j = 0; j < 24; j++) {
        float av = asrc[cq * 24 + j], dv = adst[cq * 24 + j];
        s0 += acc0[j] * av;  dd0 += acc0[j] * dv;
        s1 += acc1[j] * av;  dd1 += acc1[j] * dv;
    }
    int r0 = row0 + rp, r1 = row0 + rp + 32;
    if (r0 < n) {
#pragma unroll
        for (int j = 0; j < 24; j++) H[r0 * 96 + cq * 24 + j] = acc0[j];
        AS[r0 * 4 + cq] = s0;  AD[r0 * 4 + cq] = dd0;
    }
    if (r1 < n) {
#pragma unroll
        for (int j = 0; j < 24; j++) H[r1 * 96 + cq * 24 + j] = acc1[j];
        AS[r1 * 4 + cq] = s1;  AD[r1 * 4 + cq] = dd1;
    }
}

// ---------------- per-layer init: out=bias, m=-inf, den=0 ----------------
__global__ void k_init_layer(float* __restrict__ M, float* __restrict__ DEN,
                             float* __restrict__ OUT, const float* __restrict__ bias, int n) {
    int i = blockIdx.x * blockDim.x + threadIdx.x;
    if (i < n * 96) OUT[i] = bias[i % 96];
    if (i < n * 4) { M[i] = -INFINITY; DEN[i] = 0.f; }
}

// ---------------- edge pass 1: segment max of leaky-relu logits ----------------
__global__ void k_edge_max(const int* __restrict__ ei, const float* __restrict__ AS,
                           const float* __restrict__ AD, float* __restrict__ M,
                           int etot, int eraw) {
    int e = blockIdx.x * blockDim.x + threadIdx.x;
    if (e >= etot) return;
    int s, d;
    if (e < eraw) { s = __ldg(&ei[e]); d = __ldg(&ei[eraw + e]); }
    else          { s = d = e - eraw; }
    float4 a = *(const float4*)(AS + s * 4);
    float4 b = *(const float4*)(AD + d * 4);
    float v;
    v = a.x + b.x; v = v > 0.f ? v : 0.2f * v; atomicMaxF(&M[d * 4 + 0], v);
    v = a.y + b.y; v = v > 0.f ? v : 0.2f * v; atomicMaxF(&M[d * 4 + 1], v);
    v = a.z + b.z; v = v > 0.f ? v : 0.2f * v; atomicMaxF(&M[d * 4 + 2], v);
    v = a.w + b.w; v = v > 0.f ? v : 0.2f * v; atomicMaxF(&M[d * 4 + 3], v);
}

// ---------------- edge pass 2: ex = exp(e - m[dst]); den[dst] += ex ----------------
__global__ void k_edge_exp(const int* __restrict__ ei, const float* __restrict__ AS,
                           const float* __restrict__ AD, const float* __restrict__ M,
                           float* __restrict__ EX, float* __restrict__ DEN,
                           int etot, int eraw) {
    int e = blockIdx.x * blockDim.x + threadIdx.x;
    if (e >= etot) return;
    int s, d;
    if (e < eraw) { s = __ldg(&ei[e]); d = __ldg(&ei[eraw + e]); }
    else          { s = d = e - eraw; }
    float4 a = *(const float4*)(AS + s * 4);
    float4 b = *(const float4*)(AD + d * 4);
    float4 m = *(const float4*)(M + d * 4);
    float v; float4 ex;
    v = a.x + b.x; v = v > 0.f ? v : 0.2f * v; ex.x = expf(v - m.x);
    v = a.y + b.y; v = v > 0.f ? v : 0.2f * v; ex.y = expf(v - m.y);
    v = a.z + b.z; v = v > 0.f ? v : 0.2f * v; ex.z = expf(v - m.z);
    v = a.w + b.w; v = v > 0.f ? v : 0.2f * v; ex.w = expf(v - m.w);
    *(float4*)(EX + e * 4) = ex;
    atomicAdd(&DEN[d * 4 + 0], ex.x);
    atomicAdd(&DEN[d * 4 + 1], ex.y);
    atomicAdd(&DEN[d * 4 + 2], ex.z);
    atomicAdd(&DEN[d * 4 + 3], ex.w);
}

// ---------------- edge pass 3: out[dst] += h[src] * alpha  (warp per edge) ----------------
__global__ void k_edge_msg(const int* __restrict__ ei, const float* __restrict__ EX,
                           const float* __restrict__ DEN, const float* __restrict__ H,
                           float* __restrict__ OUT, int etot, int eraw) {
    int gtid = blockIdx.x * blockDim.x + threadIdx.x;
    int e = gtid >> 5;
    if (e >= etot) return;
    int lane = gtid & 31;
    int s, d;
    if (e < eraw) { s = __ldg(&ei[e]); d = __ldg(&ei[eraw + e]); }
    else          { s = d = e - eraw; }
    float wv = 0.f;
    if (lane < 4) wv = EX[e * 4 + lane] / (DEN[d * 4 + lane] + 1e-16f);
    float w0 = __shfl_sync(0xffffffffu, wv, 0);
    float w1 = __shfl_sync(0xffffffffu, wv, 1);
    float w2 = __shfl_sync(0xffffffffu, wv, 2);
    float w3 = __shfl_sync(0xffffffffu, wv, 3);
    int c0 = lane, c1 = lane + 32, c2 = lane + 64;
    float ww0 = (c0 < 24) ? w0 : w1;
    float ww1 = (c1 < 48) ? w1 : w2;
    float ww2 = (c2 < 72) ? w2 : w3;
    atomicAdd(&OUT[d * 96 + c0], H[s * 96 + c0] * ww0);
    atomicAdd(&OUT[d * 96 + c1], H[s * 96 + c1] * ww1);
    atomicAdd(&OUT[d * 96 + c2], H[s * 96 + c2] * ww2);
}

// ---------------- elu in place ----------------
__global__ void k_elu(float* __restrict__ X, int total) {
    int i = blockIdx.x * blockDim.x + threadIdx.x;
    if (i < total) {
        float v = X[i];
        X[i] = v > 0.f ? v : expm1f(v);
    }
}

// ---------------- pooling init ----------------
__global__ void k_init_pool(float* __restrict__ GM, float* __restrict__ GDEN, float* __restrict__ POOL) {
    int i = blockIdx.x * blockDim.x + threadIdx.x;
    if (i < GG) { GM[i] = -INFINITY; GDEN[i] = 0.f; }
    if (i < GG * 96) POOL[i] = 0.f;
}

// ---------------- gate MLP (warp per node) + segment max ----------------
__global__ void k_gate(const float* __restrict__ H, const float* __restrict__ gw1,
                       const float* __restrict__ gb1, const float* __restrict__ gw2,
                       const float* __restrict__ gb2, const int* __restrict__ batch,
                       float* __restrict__ GATE, float* __restrict__ GM, int n) {
    int gtid = blockIdx.x * blockDim.x + threadIdx.x;
    int node = gtid >> 5, lane = gtid & 31;
    if (node >= n) return;
    const float* hr = H + node * 96;
    float h0 = 0.f, h1 = 0.f;
    for (int k = 0; k < 96; k++) {
        float hv = __ldg(&hr[k]);
        h0 += hv * gw1[k * 48 + lane];
        if (lane < 16) h1 += hv * gw1[k * 48 + 32 + lane];
    }
    float g = fmaxf(h0 + gb1[lane], 0.f) * gw2[lane];
    if (lane < 16) g += fmaxf(h1 + gb1[32 + lane], 0.f) * gw2[32 + lane];
#pragma unroll
    for (int o = 16; o > 0; o >>= 1) g += __shfl_xor_sync(0xffffffffu, g, o);
    if (lane == 0) {
        g += gb2[0];
        GATE[node] = g;
        atomicMaxF(&GM[batch[node]], g);
    }
}

// ---------------- gate exp + smem-aggregated denom ----------------
__global__ void k_gate_exp(const float* __restrict__ GATE, const float* __restrict__ GM,
                           const int* __restrict__ batch, float* __restrict__ GE,
                           float* __restrict__ GDEN, int n) {
    __shared__ float sden[GG];
    for (int i = threadIdx.x; i < GG; i += blockDim.x) sden[i] = 0.f;
    __syncthreads();
    int i = blockIdx.x * blockDim.x + threadIdx.x;
    if (i < n) {
        int b = batch[i];
        float m = GM[b];
        if (m == -INFINITY) m = 0.f;
        float e = expf(GATE[i] - m);
        GE[i] = e;
        atomicAdd(&sden[b], e);
    }
    __syncthreads();
    for (int i2 = threadIdx.x; i2 < GG; i2 += blockDim.x)
        if (sden[i2] != 0.f) atomicAdd(&GDEN[i2], sden[i2]);
}

// ---------------- weighted pooling (block-local smem partials) ----------------
__global__ void k_pool(const float* __restrict__ H, const float* __restrict__ GE,
                       const float* __restrict__ GDEN, const int* __restrict__ batch,
                       float* __restrict__ POOL, int n) {
    __shared__ float sp[GG * 96];
    __shared__ float wn[128];
    __shared__ int gn[128];
    for (int i = threadIdx.x; i < GG * 96; i += 256) sp[i] = 0.f;
    int base = blockIdx.x * 128;
    int nb = min(128, n - base);
    if ((int)threadIdx.x < nb) {
        int node = base + threadIdx.x;
        int b = batch[node];
        gn[threadIdx.x] = b;
        wn[threadIdx.x] = GE[node] / (GDEN[b] + 1e-16f);
    }
    __syncthreads();
    for (int idx = threadIdx.x; idx < nb * 96; idx += 256) {
        int ni = idx / 96, c = idx - ni * 96;
        atomicAdd(&sp[gn[ni] * 96 + c], H[(base + ni) * 96 + c] * wn[ni]);
    }
    __syncthreads();
    int gmin = gn[0], gmax = gn[nb - 1];
    for (int i = threadIdx.x; i < (gmax - gmin + 1) * 96; i += 256) {
        int g = gmin + i / 96, c = i % 96;
        atomicAdd(&POOL[g * 96 + c], sp[g * 96 + c]);
    }
}

// ---------------- final MLP: [64,96] -> relu -> [64,3] ----------------
__global__ void k_final(const float* __restrict__ POOL, const float* __restrict__ fw1,
                        const float* __restrict__ fb1, const float* __restrict__ fw2,
                        const float* __restrict__ fb2, float* __restrict__ out) {
    __shared__ float pr[96];
    __shared__ float hid[96];
    int g = blockIdx.x, j = threadIdx.x;
    pr[j] = POOL[g * 96 + j];
    __syncthreads();
    float a = fb1[j];
#pragma unroll 8
    for (int k = 0; k < 96; k++) a += pr[k] * fw1[k * 96 + j];
    hid[j] = fmaxf(a, 0.f);
    __syncthreads();
    if (j < 3) {
        float o = fb2[j];
        for (int k = 0; k < 96; k++) o += hid[k] * fw2[k * 3 + j];
        out[g * 3 + j] = o;
    }
}

// ---------------- host ----------------
extern "C" void kernel_launch(void* const* d_in, const int* in_sizes, int n_in,
                              void* d_out, int out_size) {
    const float* x     = (const float*)d_in[0];
    const int*   ei    = (const int*)d_in[1];
    const int*   batch = (const int*)d_in[2];
    int idx = 3;
    if (n_in > 3 && in_sizes[3] == 1) idx = 4;   // skip num_graphs scalar if present
    const float* W1  = (const float*)d_in[idx++];
    const float* as1 = (const float*)d_in[idx++];
    const float* ad1 = (const float*)d_in[idx++];
    const float* b1  = (const float*)d_in[idx++];
    const float* W2  = (const float*)d_in[idx++];
    const float* as2 = (const float*)d_in[idx++];
    const float* ad2 = (const float*)d_in[idx++];
    const float* b2  = (const float*)d_in[idx++];
    const float* gw1 = (const float*)d_in[idx++];
    const float* gb1 = (const float*)d_in[idx++];
    const float* gw2 = (const float*)d_in[idx++];
    const float* gb2 = (const float*)d_in[idx++];
    const float* fw1 = (const float*)d_in[idx++];
    const float* fb1 = (const float*)d_in[idx++];
    const float* fw2 = (const float*)d_in[idx++];
    const float* fb2 = (const float*)d_in[idx++];

    int n    = in_sizes[0] / 128;
    int eraw = in_sizes[1] / 2;
    int etot = eraw + n;

    float *h, *o, *as_, *ad_, *m, *den, *ex, *gate, *ge, *gm, *gden, *pool;
    cudaGetSymbolAddress((void**)&h,    d_h);
    cudaGetSymbolAddress((void**)&o,    d_o);
    cudaGetSymbolAddress((void**)&as_,  d_as);
    cudaGetSymbolAddress((void**)&ad_,  d_ad);
    cudaGetSymbolAddress((void**)&m,    d_m);
    cudaGetSymbolAddress((void**)&den,  d_den);
    cudaGetSymbolAddress((void**)&ex,   d_ex);
    cudaGetSymbolAddress((void**)&gate, d_gate);
    cudaGetSymbolAddress((void**)&ge,   d_ge);
    cudaGetSymbolAddress((void**)&gm,   d_gm);
    cudaGetSymbolAddress((void**)&gden, d_gden);
    cudaGetSymbolAddress((void**)&pool, d_pool);

    int gElem  = (n * 96 + 255) / 256;
    int gEdge  = (etot + 255) / 256;
    int gMsg   = (etot * 32 + 255) / 256;
    int gGemm  = (n + 63) / 64;
    int gGate  = (n * 32 + 255) / 256;
    int gNode  = (n + 255) / 256;
    int gPool  = (n + 127) / 128;

    // ---- layer 1 ----
    k_gemm_alpha<<<gGemm, 128>>>(x, W1, as1, ad1, h, as_, ad_, n, 128);
    k_init_layer<<<gElem, 256>>>(m, den, o, b1, n);
    k_edge_max<<<gEdge, 256>>>(ei, as_, ad_, m, etot, eraw);
    k_edge_exp<<<gEdge, 256>>>(ei, as_, ad_, m, ex, den, etot, eraw);
    k_edge_msg<<<gMsg, 256>>>(ei, ex, den, h, o, etot, eraw);
    k_elu<<<gElem, 256>>>(o, n * 96);

    // ---- layer 2 ----
    k_gemm_alpha<<<gGemm, 128>>>(o, W2, as2, ad2, h, as_, ad_, n, 96);
    k_init_layer<<<gElem, 256>>>(m, den, o, b2, n);
    k_edge_max<<<gEdge, 256>>>(ei, as_, ad_, m, etot, eraw);
    k_edge_exp<<<gEdge, 256>>>(ei, as_, ad_, m, ex, den, etot, eraw);
    k_edge_msg<<<gMsg, 256>>>(ei, ex, den, h, o, etot, eraw);
    k_elu<<<gElem, 256>>>(o, n * 96);

    // ---- global attention pool + final MLP ----
    k_init_pool<<<(GG * 96 + 255) / 256, 256>>>(gm, gden, pool);
    k_gate<<<gGate, 256>>>(o, gw1, gb1, gw2, gb2, batch, gate, gm, n);
    k_gate_exp<<<gNode, 256>>>(gate, gm, batch, ge, gden, n);
    k_pool<<<gPool, 256>>>(o, ge, gden, batch, pool, n);
    k_final<<<GG, 96>>>(pool, fw1, fb1, fw2, fb2, (float*)d_out);
}

// round 2
// speedup vs baseline: 1.2459x; 1.2459x over previous
#include <cuda_runtime.h>
#include <math.h>

#define NN 50000
#define EE 800000
#define ETOT (EE + NN)
#define GG 64

// ---------------- scratch ----------------
__device__ float d_h[NN * 96];      // GEMM output (message source)
__device__ float d_o[NN * 96];      // aggregation output / next layer input
__device__ float d_as[NN * 4];
__device__ float d_ad[NN * 4];
__device__ float d_den[NN * 4];
__device__ float d_w[ETOT * 4];     // per-edge per-head exp weights (unnormalized)
__device__ int   d_deg[NN];         // degree, then scatter cursor
__device__ int   d_off[NN + 1];     // CSR offsets
__device__ int   d_srcs[ETOT];      // src ids sorted by dst
__device__ float d_gate[NN];
__device__ float d_ge[NN];
__device__ float d_gm[GG];
__device__ float d_gden[GG];
__device__ float d_pool[GG * 96];

__device__ __forceinline__ void atomicMaxF(float* a, float v) {
    if (v >= 0.f) atomicMax((int*)a, __float_as_int(v));
    else          atomicMin((unsigned int*)a, __float_as_uint(v));
}

// ================= CSR build =================
__global__ void k_hist(const int* __restrict__ ei, int* __restrict__ deg, int etot, int eraw) {
    int e = blockIdx.x * blockDim.x + threadIdx.x;
    if (e >= etot) return;
    int d = (e < eraw) ? __ldg(&ei[eraw + e]) : e - eraw;
    atomicAdd(&deg[d], 1);
}

// one block, 1024 threads: exclusive scan of deg -> off (and cursor copy into deg)
__global__ void k_scan(int* __restrict__ deg, int* __restrict__ off, int n, int etot) {
    __shared__ int ssum[1024];
    int t = threadIdx.x;
    int chunk = (n + 1023) / 1024;
    int base = t * chunk;
    int local = 0;
    for (int i = 0; i < chunk; i++) {
        int idx = base + i;
        if (idx < n) local += deg[idx];
    }
    ssum[t] = local;
    __syncthreads();
    for (int ofs = 1; ofs < 1024; ofs <<= 1) {
        int v = (t >= ofs) ? ssum[t - ofs] : 0;
        __syncthreads();
        ssum[t] += v;
        __syncthreads();
    }
    int run = (t > 0) ? ssum[t - 1] : 0;
    for (int i = 0; i < chunk; i++) {
        int idx = base + i;
        if (idx < n) {
            int dv = deg[idx];
            off[idx] = run;
            deg[idx] = run;   // cursor
            run += dv;
        }
    }
    if (t == 1023) off[n] = etot;
}

__global__ void k_scatter(const int* __restrict__ ei, int* __restrict__ cur,
                          int* __restrict__ srcs, int etot, int eraw) {
    int e = blockIdx.x * blockDim.x + threadIdx.x;
    if (e >= etot) return;
    int s, d;
    if (e < eraw) { s = __ldg(&ei[e]); d = __ldg(&ei[eraw + e]); }
    else          { s = d = e - eraw; }
    int pos = atomicAdd(&cur[d], 1);
    srcs[pos] = s;
}

// ================= GEMM + fused attention-alpha epilogue =================
__global__ void k_gemm_alpha(const float* __restrict__ A, const float* __restrict__ W,
                             const float* __restrict__ asrc, const float* __restrict__ adst,
                             float* __restrict__ H, float* __restrict__ AS, float* __restrict__ AD,
                             int n, int K) {
    __shared__ float As[64][33];
    __shared__ float Bs[32][96];
    int t = threadIdx.x;          // 128 threads
    int rp = t & 31, cq = t >> 5;
    int row0 = blockIdx.x * 64;
    float acc0[24], acc1[24];
#pragma unroll
    for (int j = 0; j < 24; j++) { acc0[j] = 0.f; acc1[j] = 0.f; }

    for (int k0 = 0; k0 < K; k0 += 32) {
        for (int i = t; i < 64 * 32; i += 128) {
            int rr = i >> 5, kk = i & 31;
            int row = row0 + rr;
            As[rr][kk] = (row < n) ? A[row * K + k0 + kk] : 0.f;
        }
        for (int i = t; i < 32 * 96; i += 128) {
            int kk = i / 96, cc = i - kk * 96;
            Bs[kk][cc] = W[(k0 + kk) * 96 + cc];
        }
        __syncthreads();
#pragma unroll
        for (int k = 0; k < 32; k++) {
            float a0 = As[rp][k], a1 = As[rp + 32][k];
#pragma unroll
            for (int j = 0; j < 24; j++) {
                float b = Bs[k][cq * 24 + j];
                acc0[j] = fmaf(a0, b, acc0[j]);
                acc1[j] = fmaf(a1, b, acc1[j]);
            }
        }
        __syncthreads();
    }

    float s0 = 0.f, dd0 = 0.f, s1 = 0.f, dd1 = 0.f;
#pragma unroll
    for (int j = 0; j < 24; j++) {
        float av = asrc[cq * 24 + j], dv = adst[cq * 24 + j];
        s0 += acc0[j] * av;  dd0 += acc0[j] * dv;
        s1 += acc1[j] * av;  dd1 += acc1[j] * dv;
    }
    int r0 = row0 + rp, r1 = row0 + rp + 32;
    if (r0 < n) {
#pragma unroll
        for (int j = 0; j < 24; j++) H[r0 * 96 + cq * 24 + j] = acc0[j];
        AS[r0 * 4 + cq] = s0;  AD[r0 * 4 + cq] = dd0;
    }
    if (r1 < n) {
#pragma unroll
        for (int j = 0; j < 24; j++) H[r1 * 96 + cq * 24 + j] = acc1[j];
        AS[r1 * 4 + cq] = s1;  AD[r1 * 4 + cq] = dd1;
    }
}

// ================= softmax over incoming edges (warp per dst) =================
__global__ void k_softmax(const int* __restrict__ off, const int* __restrict__ srcs,
                          const float* __restrict__ AS, const float* __restrict__ AD,
                          float* __restrict__ W4, float* __restrict__ DEN, int n) {
    int gtid = blockIdx.x * blockDim.x + threadIdx.x;
    int node = gtid >> 5, lane = gtid & 31;
    if (node >= n) return;
    int beg = __ldg(&off[node]), end = __ldg(&off[node + 1]);
    float4 ad = *(const float4*)(AD + node * 4);

    float4 mx = make_float4(-INFINITY, -INFINITY, -INFINITY, -INFINITY);
    for (int e = beg + lane; e < end; e += 32) {
        int s = __ldg(&srcs[e]);
        float4 a = *(const float4*)(AS + s * 4);
        float v;
        v = a.x + ad.x; v = v > 0.f ? v : 0.2f * v; mx.x = fmaxf(mx.x, v);
        v = a.y + ad.y; v = v > 0.f ? v : 0.2f * v; mx.y = fmaxf(mx.y, v);
        v = a.z + ad.z; v = v > 0.f ? v : 0.2f * v; mx.z = fmaxf(mx.z, v);
        v = a.w + ad.w; v = v > 0.f ? v : 0.2f * v; mx.w = fmaxf(mx.w, v);
    }
#pragma unroll
    for (int o = 16; o > 0; o >>= 1) {
        mx.x = fmaxf(mx.x, __shfl_xor_sync(0xffffffffu, mx.x, o));
        mx.y = fmaxf(mx.y, __shfl_xor_sync(0xffffffffu, mx.y, o));
        mx.z = fmaxf(mx.z, __shfl_xor_sync(0xffffffffu, mx.z, o));
        mx.w = fmaxf(mx.w, __shfl_xor_sync(0xffffffffu, mx.w, o));
    }

    float4 den = make_float4(0.f, 0.f, 0.f, 0.f);
    for (int e = beg + lane; e < end; e += 32) {
        int s = __ldg(&srcs[e]);
        float4 a = *(const float4*)(AS + s * 4);
        float v; float4 ex;
        v = a.x + ad.x; v = v > 0.f ? v : 0.2f * v; ex.x = expf(v - mx.x);
        v = a.y + ad.y; v = v > 0.f ? v : 0.2f * v; ex.y = expf(v - mx.y);
        v = a.z + ad.z; v = v > 0.f ? v : 0.2f * v; ex.z = expf(v - mx.z);
        v = a.w + ad.w; v = v > 0.f ? v : 0.2f * v; ex.w = expf(v - mx.w);
        *(float4*)(W4 + e * 4) = ex;
        den.x += ex.x; den.y += ex.y; den.z += ex.z; den.w += ex.w;
    }
#pragma unroll
    for (int o = 16; o > 0; o >>= 1) {
        den.x += __shfl_xor_sync(0xffffffffu, den.x, o);
        den.y += __shfl_xor_sync(0xffffffffu, den.y, o);
        den.z += __shfl_xor_sync(0xffffffffu, den.z, o);
        den.w += __shfl_xor_sync(0xffffffffu, den.w, o);
    }
    if (lane == 0) *(float4*)(DEN + node * 4) = den;
}

// ================= aggregation (warp per dst) + fused bias + ELU =================
__global__ void k_agg(const int* __restrict__ off, const int* __restrict__ srcs,
                      const float* __restrict__ W4, const float* __restrict__ DEN,
                      const float* __restrict__ H, const float* __restrict__ bias,
                      float* __restrict__ OUT, int n) {
    int gtid = blockIdx.x * blockDim.x + threadIdx.x;
    int node = gtid >> 5, lane = gtid & 31;
    if (node >= n) return;
    int beg = __ldg(&off[node]), end = __ldg(&off[node + 1]);
    int c0 = lane, c1 = lane + 32, c2 = lane + 64;
    bool s0x = (lane < 24), s1y = (lane < 16), s2z = (lane < 8);

    float a0 = 0.f, a1 = 0.f, a2 = 0.f;
    int s = __ldg(&srcs[beg]);
    float4 w = *(const float4*)(W4 + (long)beg * 4);
    for (int e = beg; e < end; e++) {
        int sn = s; float4 wn = w;
        if (e + 1 < end) {
            s = __ldg(&srcs[e + 1]);
            w = *(const float4*)(W4 + (long)(e + 1) * 4);
        }
        float w0 = s0x ? wn.x : wn.y;
        float w1 = s1y ? wn.y : wn.z;
        float w2 = s2z ? wn.z : wn.w;
        const float* hs = H + sn * 96;
        a0 = fmaf(__ldg(&hs[c0]), w0, a0);
        a1 = fmaf(__ldg(&hs[c1]), w1, a1);
        a2 = fmaf(__ldg(&hs[c2]), w2, a2);
    }
    float4 dv = *(const float4*)(DEN + node * 4);
    float i0 = 1.f / ((s0x ? dv.x : dv.y) + 1e-16f);
    float i1 = 1.f / ((s1y ? dv.y : dv.z) + 1e-16f);
    float i2 = 1.f / ((s2z ? dv.z : dv.w) + 1e-16f);
    float v0 = a0 * i0 + __ldg(&bias[c0]);
    float v1 = a1 * i1 + __ldg(&bias[c1]);
    float v2 = a2 * i2 + __ldg(&bias[c2]);
    OUT[node * 96 + c0] = v0 > 0.f ? v0 : expm1f(v0);
    OUT[node * 96 + c1] = v1 > 0.f ? v1 : expm1f(v1);
    OUT[node * 96 + c2] = v2 > 0.f ? v2 : expm1f(v2);
}

// ================= pooling =================
__global__ void k_init_pool(float* __restrict__ GM, float* __restrict__ GDEN, float* __restrict__ POOL) {
    int i = blockIdx.x * blockDim.x + threadIdx.x;
    if (i < GG) { GM[i] = -INFINITY; GDEN[i] = 0.f; }
    if (i < GG * 96) POOL[i] = 0.f;
}

__global__ void k_gate(const float* __restrict__ H, const float* __restrict__ gw1,
                       const float* __restrict__ gb1, const float* __restrict__ gw2,
                       const float* __restrict__ gb2, const int* __restrict__ batch,
                       float* __restrict__ GATE, float* __restrict__ GM, int n) {
    int gtid = blockIdx.x * blockDim.x + threadIdx.x;
    int node = gtid >> 5, lane = gtid & 31;
    if (node >= n) return;
    const float* hr = H + node * 96;
    float h0 = 0.f, h1 = 0.f;
    for (int k = 0; k < 96; k++) {
        float hv = __ldg(&hr[k]);
        h0 += hv * gw1[k * 48 + lane];
        if (lane < 16) h1 += hv * gw1[k * 48 + 32 + lane];
    }
    float g = fmaxf(h0 + gb1[lane], 0.f) * gw2[lane];
    if (lane < 16) g += fmaxf(h1 + gb1[32 + lane], 0.f) * gw2[32 + lane];
#pragma unroll
    for (int o = 16; o > 0; o >>= 1) g += __shfl_xor_sync(0xffffffffu, g, o);
    if (lane == 0) {
        g += gb2[0];
        GATE[node] = g;
        atomicMaxF(&GM[batch[node]], g);
    }
}

__global__ void k_gate_exp(const float* __restrict__ GATE, const float* __restrict__ GM,
                           const int* __restrict__ batch, float* __restrict__ GE,
                           float* __restrict__ GDEN, int n) {
    __shared__ float sden[GG];
    for (int i = threadIdx.x; i < GG; i += blockDim.x) sden[i] = 0.f;
    __syncthreads();
    int i = blockIdx.x * blockDim.x + threadIdx.x;
    if (i < n) {
        int b = batch[i];
        float m = GM[b];
        if (m == -INFINITY) m = 0.f;
        float e = expf(GATE[i] - m);
        GE[i] = e;
        atomicAdd(&sden[b], e);
    }
    __syncthreads();
    for (int i2 = threadIdx.x; i2 < GG; i2 += blockDim.x)
        if (sden[i2] != 0.f) atomicAdd(&GDEN[i2], sden[i2]);
}

__global__ void k_pool(const float* __restrict__ H, const float* __restrict__ GE,
                       const float* __restrict__ GDEN, const int* __restrict__ batch,
                       float* __restrict__ POOL, int n) {
    __shared__ float sp[GG * 96];
    __shared__ float wn[128];
    __shared__ int gn[128];
    for (int i = threadIdx.x; i < GG * 96; i += 256) sp[i] = 0.f;
    int base = blockIdx.x * 128;
    int nb = min(128, n - base);
    if ((int)threadIdx.x < nb) {
        int node = base + threadIdx.x;
        int b = batch[node];
        gn[threadIdx.x] = b;
        wn[threadIdx.x] = GE[node] / (GDEN[b] + 1e-16f);
    }
    __syncthreads();
    for (int idx = threadIdx.x; idx < nb * 96; idx += 256) {
        int ni = idx / 96, c = idx - ni * 96;
        atomicAdd(&sp[gn[ni] * 96 + c], H[(base + ni) * 96 + c] * wn[ni]);
    }
    __syncthreads();
    int gmin = gn[0], gmax = gn[nb - 1];
    for (int i = threadIdx.x; i < (gmax - gmin + 1) * 96; i += 256) {
        int g = gmin + i / 96, c = i % 96;
        atomicAdd(&POOL[g * 96 + c], sp[g * 96 + c]);
    }
}

__global__ void k_final(const float* __restrict__ POOL, const float* __restrict__ fw1,
                        const float* __restrict__ fb1, const float* __restrict__ fw2,
                        const float* __restrict__ fb2, float* __restrict__ out) {
    __shared__ float pr[96];
    __shared__ float hid[96];
    int g = blockIdx.x, j = threadIdx.x;
    pr[j] = POOL[g * 96 + j];
    __syncthreads();
    float a = fb1[j];
#pragma unroll 8
    for (int k = 0; k < 96; k++) a += pr[k] * fw1[k * 96 + j];
    hid[j] = fmaxf(a, 0.f);
    __syncthreads();
    if (j < 3) {
        float o = fb2[j];
        for (int k = 0; k < 96; k++) o += hid[k] * fw2[k * 3 + j];
        out[g * 3 + j] = o;
    }
}

// ================= host =================
extern "C" void kernel_launch(void* const* d_in, const int* in_sizes, int n_in,
                              void* d_out, int out_size) {
    const float* x     = (const float*)d_in[0];
    const int*   ei    = (const int*)d_in[1];
    const int*   batch = (const int*)d_in[2];
    int idx = 3;
    if (n_in > 3 && in_sizes[3] == 1) idx = 4;   // skip num_graphs scalar if present
    const float* W1  = (const float*)d_in[idx++];
    const float* as1 = (const float*)d_in[idx++];
    const float* ad1 = (const float*)d_in[idx++];
    const float* b1  = (const float*)d_in[idx++];
    const float* W2  = (const float*)d_in[idx++];
    const float* as2 = (const float*)d_in[idx++];
    const float* ad2 = (const float*)d_in[idx++];
    const float* b2  = (const float*)d_in[idx++];
    const float* gw1 = (const float*)d_in[idx++];
    const float* gb1 = (const float*)d_in[idx++];
    const float* gw2 = (const float*)d_in[idx++];
    const float* gb2 = (const float*)d_in[idx++];
    const float* fw1 = (const float*)d_in[idx++];
    const float* fb1 = (const float*)d_in[idx++];
    const float* fw2 = (const float*)d_in[idx++];
    const float* fb2 = (const float*)d_in[idx++];

    int n    = in_sizes[0] / 128;
    int eraw = in_sizes[1] / 2;
    int etot = eraw + n;

    float *h, *o, *as_, *ad_, *den, *w4, *gate, *ge, *gm, *gden, *pool;
    int *deg, *off, *srcs;
    cudaGetSymbolAddress((void**)&h,    d_h);
    cudaGetSymbolAddress((void**)&o,    d_o);
    cudaGetSymbolAddress((void**)&as_,  d_as);
    cudaGetSymbolAddress((void**)&ad_,  d_ad);
    cudaGetSymbolAddress((void**)&den,  d_den);
    cudaGetSymbolAddress((void**)&w4,   d_w);
    cudaGetSymbolAddress((void**)&gate, d_gate);
    cudaGetSymbolAddress((void**)&ge,   d_ge);
    cudaGetSymbolAddress((void**)&gm,   d_gm);
    cudaGetSymbolAddress((void**)&gden, d_gden);
    cudaGetSymbolAddress((void**)&pool, d_pool);
    cudaGetSymbolAddress((void**)&deg,  d_deg);
    cudaGetSymbolAddress((void**)&off,  d_off);
    cudaGetSymbolAddress((void**)&srcs, d_srcs);

    int gEdge = (etot + 255) / 256;
    int gWarp = (n * 32 + 255) / 256;
    int gGemm = (n + 63) / 64;
    int gNode = (n + 255) / 256;
    int gPool = (n + 127) / 128;

    // ---- CSR build (once; shared by both layers) ----
    cudaMemsetAsync(deg, 0, n * sizeof(int));
    k_hist<<<gEdge, 256>>>(ei, deg, etot, eraw);
    k_scan<<<1, 1024>>>(deg, off, n, etot);
    k_scatter<<<gEdge, 256>>>(ei, deg, srcs, etot, eraw);

    // ---- layer 1 ----
    k_gemm_alpha<<<gGemm, 128>>>(x, W1, as1, ad1, h, as_, ad_, n, 128);
    k_softmax<<<gWarp, 256>>>(off, srcs, as_, ad_, w4, den, n);
    k_agg<<<gWarp, 256>>>(off, srcs, w4, den, h, b1, o, n);

    // ---- layer 2 ----
    k_gemm_alpha<<<gGemm, 128>>>(o, W2, as2, ad2, h, as_, ad_, n, 96);
    k_softmax<<<gWarp, 256>>>(off, srcs, as_, ad_, w4, den, n);
    k_agg<<<gWarp, 256>>>(off, srcs, w4, den, h, b2, o, n);

    // ---- global attention pool + final MLP ----
    k_init_pool<<<(GG * 96 + 255) / 256, 256>>>(gm, gden, pool);
    k_gate<<<gWarp, 256>>>(o, gw1, gb1, gw2, gb2, batch, gate, gm, n);
    k_gate_exp<<<gNode, 256>>>(gate, gm, batch, ge, gden, n);
    k_pool<<<gPool, 256>>>(o, ge, gden, batch, pool, n);
    k_final<<<GG, 96>>>(pool, fw1, fb1, fw2, fb2, (float*)d_out);
}

// round 4
// speedup vs baseline: 1.3599x; 1.0915x over previous
#include <cuda_runtime.h>
#include <math.h>

#define NN 50000
#define EE 800000
#define ETOT (EE + NN)
#define GG 64

// ---------------- scratch ----------------
__device__ float d_h[NN * 96];
__device__ float d_o[NN * 96];
__device__ float d_as[NN * 4];
__device__ float d_ad[NN * 4];
__device__ float d_den[NN * 4];
__device__ float d_w[ETOT * 4];
__device__ int   d_deg[NN];
__device__ int   d_off[NN + 1];
__device__ int   d_srcs[ETOT];
__device__ float d_gate[NN];
__device__ float d_ge[NN];
__device__ float d_gm[GG];
__device__ float d_gden[GG];
__device__ float d_pool[GG * 96];

__device__ __forceinline__ void atomicMaxF(float* a, float v) {
    if (v >= 0.f) atomicMax((int*)a, __float_as_int(v));
    else          atomicMin((unsigned int*)a, __float_as_uint(v));
}

// f32x2 packed helpers
__device__ __forceinline__ unsigned long long pk2(float x, float y) {
    unsigned long long r;
    asm("mov.b64 %0, {%1, %2};" : "=l"(r) : "f"(x), "f"(y));
    return r;
}
__device__ __forceinline__ unsigned long long fma2(unsigned long long a, unsigned long long b, unsigned long long c) {
    unsigned long long d;
    asm("fma.rn.f32x2 %0, %1, %2, %3;" : "=l"(d) : "l"(a), "l"(b), "l"(c));
    return d;
}
__device__ __forceinline__ void upk2(unsigned long long v, float& x, float& y) {
    asm("mov.b64 {%0, %1}, %2;" : "=f"(x), "=f"(y) : "l"(v));
}

// ================= CSR build =================
__global__ void k_hist(const int* __restrict__ ei, int* __restrict__ deg, int etot, int eraw) {
    int e = blockIdx.x * blockDim.x + threadIdx.x;
    if (e >= etot) return;
    int d = (e < eraw) ? __ldg(&ei[eraw + e]) : e - eraw;
    atomicAdd(&deg[d], 1);
}

__global__ void k_scan(int* __restrict__ deg, int* __restrict__ off, int n, int etot) {
    __shared__ int ssum[1024];
    int t = threadIdx.x;
    int chunk = (n + 1023) / 1024;
    int base = t * chunk;
    int local = 0;
    for (int i = 0; i < chunk; i++) {
        int idx = base + i;
        if (idx < n) local += deg[idx];
    }
    ssum[t] = local;
    __syncthreads();
    for (int ofs = 1; ofs < 1024; ofs <<= 1) {
        int v = (t >= ofs) ? ssum[t - ofs] : 0;
        __syncthreads();
        ssum[t] += v;
        __syncthreads();
    }
    int run = (t > 0) ? ssum[t - 1] : 0;
    for (int i = 0; i < chunk; i++) {
        int idx = base + i;
        if (idx < n) {
            int dv = deg[idx];
            off[idx] = run;
            deg[idx] = run;
            run += dv;
        }
    }
    if (t == 1023) off[n] = etot;
}

__global__ void k_scatter(const int* __restrict__ ei, int* __restrict__ cur,
                          int* __restrict__ srcs, int etot, int eraw) {
    int e = blockIdx.x * blockDim.x + threadIdx.x;
    if (e >= etot) return;
    int s, d;
    if (e < eraw) { s = __ldg(&ei[e]); d = __ldg(&ei[eraw + e]); }
    else          { s = d = e - eraw; }
    int pos = atomicAdd(&cur[d], 1);
    srcs[pos] = s;
}

// ================= GEMM: C[n,96] = A[n,K] @ W[K,96], f32x2 =================
// 384 threads = 12 warps. warp w owns cols [w*8, w*8+8); lane owns rows lane+32f, f=0..11.
template<int K, int KC>
__global__ void __launch_bounds__(384, 1) k_gemm2(const float* __restrict__ A,
                                                  const float* __restrict__ W,
                                                  float* __restrict__ H, int n) {
    extern __shared__ float sm[];
    float* Bs = sm;              // K*96  (FULL weight matrix, global-k indexed)
    float* As = sm + K * 96;     // KC*385
    int tid = threadIdx.x;
    int w = tid >> 5, lane = tid & 31;
    int row0 = blockIdx.x * 384;

    unsigned long long acc[12][4];
#pragma unroll
    for (int f = 0; f < 12; f++)
#pragma unroll
        for (int j = 0; j < 4; j++) acc[f][j] = 0ull;

    for (int i = tid; i < K * 96; i += 384) Bs[i] = W[i];

    for (int k0 = 0; k0 < K; k0 += KC) {
        __syncthreads();
        for (int i = tid; i < 384 * KC; i += 384) {
            int k = i % KC, r = i / KC;
            int row = row0 + r;
            As[k * 385 + r] = (row < n) ? A[row * K + k0 + k] : 0.f;
        }
        __syncthreads();
#pragma unroll 4
        for (int k = 0; k < KC; k++) {
            const float* a_ = &As[k * 385 + lane];
            const float* b_ = &Bs[(k0 + k) * 96 + w * 8];   // FIX: global-k index
            float4 b0 = *(const float4*)(b_);
            float4 b1 = *(const float4*)(b_ + 4);
            unsigned long long bp0 = pk2(b0.x, b0.y);
            unsigned long long bp1 = pk2(b0.z, b0.w);
            unsigned long long bp2 = pk2(b1.x, b1.y);
            unsigned long long bp3 = pk2(b1.z, b1.w);
#pragma unroll
            for (int f = 0; f < 12; f++) {
                float av = a_[f * 32];
                unsigned long long ap = pk2(av, av);
                acc[f][0] = fma2(ap, bp0, acc[f][0]);
                acc[f][1] = fma2(ap, bp1, acc[f][1]);
                acc[f][2] = fma2(ap, bp2, acc[f][2]);
                acc[f][3] = fma2(ap, bp3, acc[f][3]);
            }
        }
    }

#pragma unroll
    for (int f = 0; f < 12; f++) {
        int row = row0 + lane + f * 32;
        if (row < n) {
            float4 o0, o1;
            upk2(acc[f][0], o0.x, o0.y);
            upk2(acc[f][1], o0.z, o0.w);
            upk2(acc[f][2], o1.x, o1.y);
            upk2(acc[f][3], o1.z, o1.w);
            float* out = H + row * 96 + w * 8;
            *(float4*)(out) = o0;
            *(float4*)(out + 4) = o1;
        }
    }
}

// ================= alpha dot products (warp per node) =================
__global__ void k_alpha(const float* __restrict__ H, const float* __restrict__ asrc,
                        const float* __restrict__ adst, float* __restrict__ AS,
                        float* __restrict__ AD, int n) {
    int gtid = blockIdx.x * blockDim.x + threadIdx.x;
    int node = gtid >> 5, lane = gtid & 31;
    if (node >= n) return;
    float ps = 0.f, pd = 0.f;
    if (lane < 24) {
        float4 h4 = *(const float4*)(H + node * 96 + lane * 4);
        float4 s4 = *(const float4*)(asrc + lane * 4);
        float4 dd4 = *(const float4*)(adst + lane * 4);
        ps = h4.x * s4.x + h4.y * s4.y + h4.z * s4.z + h4.w * s4.w;
        pd = h4.x * dd4.x + h4.y * dd4.y + h4.z * dd4.z + h4.w * dd4.w;
    }
    float s = 0.f, d = 0.f;
#pragma unroll
    for (int j = 0; j < 6; j++) {
        int srcl = lane * 6 + j;
        s += __shfl_sync(0xffffffffu, ps, srcl & 31);
        d += __shfl_sync(0xffffffffu, pd, srcl & 31);
    }
    if (lane < 4) {
        AS[node * 4 + lane] = s;
        AD[node * 4 + lane] = d;
    }
}

// ================= softmax over incoming edges (warp per dst) =================
__global__ void k_softmax(const int* __restrict__ off, const int* __restrict__ srcs,
                          const float* __restrict__ AS, const float* __restrict__ AD,
                          float* __restrict__ W4, float* __restrict__ DEN, int n) {
    int gtid = blockIdx.x * blockDim.x + threadIdx.x;
    int node = gtid >> 5, lane = gtid & 31;
    if (node >= n) return;
    int beg = __ldg(&off[node]), end = __ldg(&off[node + 1]);
    float4 ad = *(const float4*)(AD + node * 4);

    float4 mx = make_float4(-INFINITY, -INFINITY, -INFINITY, -INFINITY);
    for (int e = beg + lane; e < end; e += 32) {
        int s = __ldg(&srcs[e]);
        float4 a = *(const float4*)(AS + s * 4);
        float4 v;
        v.x = a.x + ad.x; v.x = v.x > 0.f ? v.x : 0.2f * v.x; mx.x = fmaxf(mx.x, v.x);
        v.y = a.y + ad.y; v.y = v.y > 0.f ? v.y : 0.2f * v.y; mx.y = fmaxf(mx.y, v.y);
        v.z = a.z + ad.z; v.z = v.z > 0.f ? v.z : 0.2f * v.z; mx.z = fmaxf(mx.z, v.z);
        v.w = a.w + ad.w; v.w = v.w > 0.f ? v.w : 0.2f * v.w; mx.w = fmaxf(mx.w, v.w);
        *(float4*)(W4 + e * 4) = v;   // cache logits
    }
#pragma unroll
    for (int o = 16; o > 0; o >>= 1) {
        mx.x = fmaxf(mx.x, __shfl_xor_sync(0xffffffffu, mx.x, o));
        mx.y = fmaxf(mx.y, __shfl_xor_sync(0xffffffffu, mx.y, o));
        mx.z = fmaxf(mx.z, __shfl_xor_sync(0xffffffffu, mx.z, o));
        mx.w = fmaxf(mx.w, __shfl_xor_sync(0xffffffffu, mx.w, o));
    }

    float4 den = make_float4(0.f, 0.f, 0.f, 0.f);
    for (int e = beg + lane; e < end; e += 32) {
        float4 v = *(const float4*)(W4 + e * 4);
        float4 ex;
        ex.x = expf(v.x - mx.x);
        ex.y = expf(v.y - mx.y);
        ex.z = expf(v.z - mx.z);
        ex.w = expf(v.w - mx.w);
        *(float4*)(W4 + e * 4) = ex;
        den.x += ex.x; den.y += ex.y; den.z += ex.z; den.w += ex.w;
    }
#pragma unroll
    for (int o = 16; o > 0; o >>= 1) {
        den.x += __shfl_xor_sync(0xffffffffu, den.x, o);
        den.y += __shfl_xor_sync(0xffffffffu, den.y, o);
        den.z += __shfl_xor_sync(0xffffffffu, den.z, o);
        den.w += __shfl_xor_sync(0xffffffffu, den.w, o);
    }
    if (lane == 0) *(float4*)(DEN + node * 4) = den;
}

// ================= aggregation (warp per dst, float4 lanes) + bias + ELU =================
__global__ void k_agg(const int* __restrict__ off, const int* __restrict__ srcs,
                      const float* __restrict__ W4, const float* __restrict__ DEN,
                      const float* __restrict__ H, const float* __restrict__ bias,
                      float* __restrict__ OUT, int n) {
    int gtid = blockIdx.x * blockDim.x + threadIdx.x;
    int node = gtid >> 5, lane = gtid & 31;
    if (node >= n) return;
    int beg = __ldg(&off[node]), end = __ldg(&off[node + 1]);
    bool act = lane < 24;

    float4 acc = make_float4(0.f, 0.f, 0.f, 0.f);
    int s = __ldg(&srcs[beg]);
    float4 wv = *(const float4*)(W4 + beg * 4);
    for (int e = beg; e < end; e++) {
        int sn = s; float4 wn = wv;
        if (e + 1 < end) {
            s = __ldg(&srcs[e + 1]);
            wv = *(const float4*)(W4 + (e + 1) * 4);
        }
        if (act) {
            float wh = lane < 6 ? wn.x : (lane < 12 ? wn.y : (lane < 18 ? wn.z : wn.w));
            float4 h4 = *(const float4*)(H + sn * 96 + lane * 4);
            acc.x = fmaf(h4.x, wh, acc.x);
            acc.y = fmaf(h4.y, wh, acc.y);
            acc.z = fmaf(h4.z, wh, acc.z);
            acc.w = fmaf(h4.w, wh, acc.w);
        }
    }
    if (act) {
        float4 dv = *(const float4*)(DEN + node * 4);
        float dh = lane < 6 ? dv.x : (lane < 12 ? dv.y : (lane < 18 ? dv.z : dv.w));
        float inv = 1.f / (dh + 1e-16f);
        float4 b4 = *(const float4*)(bias + lane * 4);
        float4 o;
        o.x = acc.x * inv + b4.x;  o.x = o.x > 0.f ? o.x : expm1f(o.x);
        o.y = acc.y * inv + b4.y;  o.y = o.y > 0.f ? o.y : expm1f(o.y);
        o.z = acc.z * inv + b4.z;  o.z = o.z > 0.f ? o.z : expm1f(o.z);
        o.w = acc.w * inv + b4.w;  o.w = o.w > 0.f ? o.w : expm1f(o.w);
        *(float4*)(OUT + node * 96 + lane * 4) = o;
    }
}

// ================= gate MLP: smem weights, 2 nodes per warp =================
__global__ void k_gate(const float* __restrict__ H, const float* __restrict__ gw1,
                       const float* __restrict__ gb1, const float* __restrict__ gw2,
                       const float* __restrict__ gb2, const int* __restrict__ batch,
                       float* __restrict__ GATE, float* __restrict__ GM, int n) {
    __shared__ float sw1[96 * 48];
    __shared__ float sb1[48], sg2[48];
    int tid = threadIdx.x;
    for (int i = tid; i < 96 * 48; i += 256) sw1[i] = gw1[i];
    if (tid < 48) { sb1[tid] = gb1[tid]; sg2[tid] = gw2[tid]; }
    __syncthreads();
    int w = tid >> 5, lane = tid & 31;
    int base = blockIdx.x * 64;
    for (int it = 0; it < 4; it++) {
        int nodeA = base + it * 16 + w * 2;
        int nodeB = nodeA + 1;
        bool vA = nodeA < n, vB = nodeB < n;
        if (!vA) return;
        float a0 = 0.f, a1 = 0.f, b0 = 0.f, b1 = 0.f;
        const float* hA = H + nodeA * 96;
        const float* hB = H + nodeB * 96;
        for (int k = 0; k < 96; k++) {
            float w0 = sw1[k * 48 + lane];
            float hv0 = __ldg(&hA[k]);
            a0 = fmaf(hv0, w0, a0);
            float hv1 = vB ? __ldg(&hB[k]) : 0.f;
            b0 = fmaf(hv1, w0, b0);
            if (lane < 16) {
                float w1 = sw1[k * 48 + 32 + lane];
                a1 = fmaf(hv0, w1, a1);
                b1 = fmaf(hv1, w1, b1);
            }
        }
        float gA = fmaxf(a0 + sb1[lane], 0.f) * sg2[lane];
        float gB = fmaxf(b0 + sb1[lane], 0.f) * sg2[lane];
        if (lane < 16) {
            gA += fmaxf(a1 + sb1[32 + lane], 0.f) * sg2[32 + lane];
            gB += fmaxf(b1 + sb1[32 + lane], 0.f) * sg2[32 + lane];
        }
#pragma unroll
        for (int o = 16; o > 0; o >>= 1) {
            gA += __shfl_xor_sync(0xffffffffu, gA, o);
            gB += __shfl_xor_sync(0xffffffffu, gB, o);
        }
        if (lane == 0) {
            gA += gb2[0];
            GATE[nodeA] = gA;
            atomicMaxF(&GM[batch[nodeA]], gA);
        }
        if (lane == 1 && vB) {
            gB += gb2[0];
            GATE[nodeB] = gB;
            atomicMaxF(&GM[batch[nodeB]], gB);
        }
    }
}

__global__ void k_init_gm(float* __restrict__ GM, float* __restrict__ GDEN) {
    int i = threadIdx.x;
    if (i < GG) { GM[i] = -INFINITY; GDEN[i] = 0.f; }
}

__global__ void k_gate_exp(const float* __restrict__ GATE, const float* __restrict__ GM,
                           const int* __restrict__ batch, float* __restrict__ GE,
                           float* __restrict__ GDEN, int n) {
    __shared__ float sden[GG];
    for (int i = threadIdx.x; i < GG; i += blockDim.x) sden[i] = 0.f;
    __syncthreads();
    int i = blockIdx.x * blockDim.x + threadIdx.x;
    if (i < n) {
        int b = batch[i];
        float m = GM[b];
        if (m == -INFINITY) m = 0.f;
        float e = expf(GATE[i] - m);
        GE[i] = e;
        atomicAdd(&sden[b], e);
    }
    __syncthreads();
    for (int i2 = threadIdx.x; i2 < GG; i2 += blockDim.x)
        if (sden[i2] != 0.f) atomicAdd(&GDEN[i2], sden[i2]);
}

// ================= pooling: one block per graph =================
__global__ void k_pool(const float* __restrict__ H, const float* __restrict__ GE,
                       const float* __restrict__ GDEN, const int* __restrict__ batch,
                       float* __restrict__ POOL, int n) {
    __shared__ float red[192];
    int g = blockIdx.x;
    int tid = threadIdx.x;           // 192 threads
    int lo = 0, hi = n;
    while (lo < hi) { int mid = (lo + hi) >> 1; if (__ldg(&batch[mid]) < g) lo = mid + 1; else hi = mid; }
    int beg = lo;
    lo = beg; hi = n;
    while (lo < hi) { int mid = (lo + hi) >> 1; if (__ldg(&batch[mid]) < g + 1) lo = mid + 1; else hi = mid; }
    int end = lo;

    float invden = 1.f / (GDEN[g] + 1e-16f);
    int half = tid / 96, c = tid - half * 96;
    float acc = 0.f;
    for (int node = beg + half; node < end; node += 2) {
        float wv = __ldg(&GE[node]) * invden;
        acc = fmaf(__ldg(&H[node * 96 + c]), wv, acc);
    }
    red[tid] = acc;
    __syncthreads();
    if (tid < 96) POOL[g * 96 + tid] = red[tid] + red[tid + 96];
}

__global__ void k_final(const float* __restrict__ POOL, const float* __restrict__ fw1,
                        const float* __restrict__ fb1, const float* __restrict__ fw2,
                        const float* __restrict__ fb2, float* __restrict__ out) {
    __shared__ float pr[96];
    __shared__ float hid[96];
    int g = blockIdx.x, j = threadIdx.x;
    pr[j] = POOL[g * 96 + j];
    __syncthreads();
    float a = fb1[j];
#pragma unroll 8
    for (int k = 0; k < 96; k++) a += pr[k] * fw1[k * 96 + j];
    hid[j] = fmaxf(a, 0.f);
    __syncthreads();
    if (j < 3) {
        float o = fb2[j];
        for (int k = 0; k < 96; k++) o += hid[k] * fw2[k * 3 + j];
        out[g * 3 + j] = o;
    }
}

// ================= host =================
extern "C" void kernel_launch(void* const* d_in, const int* in_sizes, int n_in,
                              void* d_out, int out_size) {
    const float* x     = (const float*)d_in[0];
    const int*   ei    = (const int*)d_in[1];
    const int*   batch = (const int*)d_in[2];
    int idx = 3;
    if (n_in > 3 && in_sizes[3] == 1) idx = 4;
    const float* W1  = (const float*)d_in[idx++];
    const float* as1 = (const float*)d_in[idx++];
    const float* ad1 = (const float*)d_in[idx++];
    const float* b1  = (const float*)d_in[idx++];
    const float* W2  = (const float*)d_in[idx++];
    const float* as2 = (const float*)d_in[idx++];
    const float* ad2 = (const float*)d_in[idx++];
    const float* b2  = (const float*)d_in[idx++];
    const float* gw1 = (const float*)d_in[idx++];
    const float* gb1 = (const float*)d_in[idx++];
    const float* gw2 = (const float*)d_in[idx++];
    const float* gb2 = (const float*)d_in[idx++];
    const float* fw1 = (const float*)d_in[idx++];
    const float* fb1 = (const float*)d_in[idx++];
    const float* fw2 = (const float*)d_in[idx++];
    const float* fb2 = (const float*)d_in[idx++];

    int n    = in_sizes[0] / 128;
    int eraw = in_sizes[1] / 2;
    int etot = eraw + n;

    float *h, *o, *as_, *ad_, *den, *w4, *gate, *ge, *gm, *gden, *pool;
    int *deg, *off, *srcs;
    cudaGetSymbolAddress((void**)&h,    d_h);
    cudaGetSymbolAddress((void**)&o,    d_o);
    cudaGetSymbolAddress((void**)&as_,  d_as);
    cudaGetSymbolAddress((void**)&ad_,  d_ad);
    cudaGetSymbolAddress((void**)&den,  d_den);
    cudaGetSymbolAddress((void**)&w4,   d_w);
    cudaGetSymbolAddress((void**)&gate, d_gate);
    cudaGetSymbolAddress((void**)&ge,   d_ge);
    cudaGetSymbolAddress((void**)&gm,   d_gm);
    cudaGetSymbolAddress((void**)&gden, d_gden);
    cudaGetSymbolAddress((void**)&pool, d_pool);
    cudaGetSymbolAddress((void**)&deg,  d_deg);
    cudaGetSymbolAddress((void**)&off,  d_off);
    cudaGetSymbolAddress((void**)&srcs, d_srcs);

    int smem1 = (128 * 96 + 64 * 385) * 4;
    int smem2 = (96 * 96 + 96 * 385) * 4;
    cudaFuncSetAttribute(k_gemm2<128, 64>, cudaFuncAttributeMaxDynamicSharedMemorySize, smem1);
    cudaFuncSetAttribute(k_gemm2<96, 96>,  cudaFuncAttributeMaxDynamicSharedMemorySize, smem2);

    int gEdge = (etot + 255) / 256;
    int gWarp = (n * 32 + 255) / 256;
    int gGemm = (n + 383) / 384;
    int gNode = (n + 255) / 256;

    // ---- CSR build ----
    cudaMemsetAsync(deg, 0, n * sizeof(int));
    k_hist<<<gEdge, 256>>>(ei, deg, etot, eraw);
    k_scan<<<1, 1024>>>(deg, off, n, etot);
    k_scatter<<<gEdge, 256>>>(ei, deg, srcs, etot, eraw);

    // ---- layer 1 ----
    k_gemm2<128, 64><<<gGemm, 384, smem1>>>(x, W1, h, n);
    k_alpha<<<gWarp, 256>>>(h, as1, ad1, as_, ad_, n);
    k_softmax<<<gWarp, 256>>>(off, srcs, as_, ad_, w4, den, n);
    k_agg<<<gWarp, 256>>>(off, srcs, w4, den, h, b1, o, n);

    // ---- layer 2 ----
    k_gemm2<96, 96><<<gGemm, 384, smem2>>>(o, W2, h, n);
    k_alpha<<<gWarp, 256>>>(h, as2, ad2, as_, ad_, n);
    k_softmax<<<gWarp, 256>>>(off, srcs, as_, ad_, w4, den, n);
    k_agg<<<gWarp, 256>>>(off, srcs, w4, den, h, b2, o, n);

    // ---- global attention pool + final MLP ----
    k_init_gm<<<1, GG>>>(gm, gden);
    k_gate<<<(n + 63) / 64, 256>>>(o, gw1, gb1, gw2, gb2, batch, gate, gm, n);
    k_gate_exp<<<gNode, 256>>>(gate, gm, batch, ge, gden, n);
    k_pool<<<GG, 192>>>(o, ge, gden, batch, pool, n);
    k_final<<<GG, 96>>>(pool, fw1, fb1, fw2, fb2, (float*)d_out);
}

// round 5
// speedup vs baseline: 1.7055x; 1.2541x over previous
#include <cuda_runtime.h>
#include <math.h>

#define NN 50000
#define EE 800000
#define ETOT (EE + NN)
#define GG 64

// ---------------- scratch ----------------
__device__ float d_h[NN * 96];
__device__ float d_o[NN * 96];
__device__ float d_as[NN * 4];
__device__ float d_ad[NN * 4];
__device__ float d_den[NN * 4];
__device__ float d_w[ETOT * 4];
__device__ int   d_deg[NN];
__device__ int   d_part[NN];
__device__ int   d_bsum[64];
__device__ int   d_off[NN + 1];
__device__ int   d_srcs[ETOT];
__device__ float d_gate[NN];
__device__ float d_ge[NN];
__device__ float d_gm[GG];
__device__ float d_gden[GG];
__device__ float d_pool[GG * 96];

__device__ __forceinline__ void atomicMaxF(float* a, float v) {
    if (v >= 0.f) atomicMax((int*)a, __float_as_int(v));
    else          atomicMin((unsigned int*)a, __float_as_uint(v));
}

typedef unsigned long long ull;
__device__ __forceinline__ ull pk2(float x, float y) {
    ull r;
    asm("mov.b64 %0, {%1, %2};" : "=l"(r) : "f"(x), "f"(y));
    return r;
}
__device__ __forceinline__ ull fma2(ull a, ull b, ull c) {
    ull d;
    asm("fma.rn.f32x2 %0, %1, %2, %3;" : "=l"(d) : "l"(a), "l"(b), "l"(c));
    return d;
}
__device__ __forceinline__ void upk2(ull v, float& x, float& y) {
    asm("mov.b64 {%0, %1}, %2;" : "=f"(x), "=f"(y) : "l"(v));
}

// ================= CSR build =================
__global__ void k_hist(const int* __restrict__ ei, int* __restrict__ deg, int etot, int eraw) {
    int e = blockIdx.x * blockDim.x + threadIdx.x;
    if (e >= etot) return;
    int d = (e < eraw) ? __ldg(&ei[eraw + e]) : e - eraw;
    atomicAdd(&deg[d], 1);
}

// parallel scan, stage A: per-1024-block exclusive scan + block totals
__global__ void k_scanA(const int* __restrict__ deg, int* __restrict__ part,
                        int* __restrict__ bsum, int n) {
    __shared__ int wsum[32];
    int t = threadIdx.x;
    int i = blockIdx.x * 1024 + t;
    int v = (i < n) ? deg[i] : 0;
    int lane = t & 31, w = t >> 5;
    int x = v;
#pragma unroll
    for (int o = 1; o < 32; o <<= 1) {
        int y = __shfl_up_sync(0xffffffffu, x, o);
        if (lane >= o) x += y;
    }
    if (lane == 31) wsum[w] = x;
    __syncthreads();
    if (w == 0) {
        int s = wsum[lane];
#pragma unroll
        for (int o = 1; o < 32; o <<= 1) {
            int y = __shfl_up_sync(0xffffffffu, s, o);
            if (lane >= o) s += y;
        }
        wsum[lane] = s;
    }
    __syncthreads();
    int woff = (w > 0) ? wsum[w - 1] : 0;
    if (i < n) part[i] = x - v + woff;
    if (t == 0) bsum[blockIdx.x] = wsum[31];
}

// stage B: scan the (<=64) block totals
__global__ void k_scanB(int* __restrict__ bsum, int nb) {
    if (threadIdx.x == 0) {
        int run = 0;
        for (int i = 0; i < nb; i++) { int v = bsum[i]; bsum[i] = run; run += v; }
    }
}

// stage C: final offsets + cursor copy
__global__ void k_scanC(const int* __restrict__ part, const int* __restrict__ bsum,
                        int* __restrict__ off, int* __restrict__ cur, int n, int etot) {
    int i = blockIdx.x * 1024 + threadIdx.x;
    if (i < n) {
        int v = part[i] + bsum[blockIdx.x];
        off[i] = v;
        cur[i] = v;
    }
    if (i == 0) off[n] = etot;
}

__global__ void k_scatter(const int* __restrict__ ei, int* __restrict__ cur,
                          int* __restrict__ srcs, int etot, int eraw) {
    int e = blockIdx.x * blockDim.x + threadIdx.x;
    if (e >= etot) return;
    int s, d;
    if (e < eraw) { s = __ldg(&ei[e]); d = __ldg(&ei[eraw + e]); }
    else          { s = d = e - eraw; }
    int pos = atomicAdd(&cur[d], 1);
    srcs[pos] = s;
}

// ================= GEMM: C[n,96] = A[n,K] @ W[K,96], f32x2, 2 blocks/SM =================
// TM=192 rows/block, 384 threads (12 warps). warp w owns cols [w*8,w*8+8);
// lane owns rows lane+32f, f=0..5.
template<int K, int KC>
__global__ void __launch_bounds__(384, 2) k_gemm2(const float* __restrict__ A,
                                                  const float* __restrict__ W,
                                                  float* __restrict__ H, int n) {
    extern __shared__ float sm[];
    float* Bs = sm;              // K*96 (full weights, global-k)
    float* As = sm + K * 96;     // KC*193
    int tid = threadIdx.x;
    int w = tid >> 5, lane = tid & 31;
    int row0 = blockIdx.x * 192;

    ull acc[6][4];
#pragma unroll
    for (int f = 0; f < 6; f++)
#pragma unroll
        for (int j = 0; j < 4; j++) acc[f][j] = 0ull;

    for (int i = tid; i < K * 96; i += 384) Bs[i] = W[i];

    for (int k0 = 0; k0 < K; k0 += KC) {
        __syncthreads();
        for (int i = tid; i < 192 * KC; i += 384) {
            int k = i % KC, r = i / KC;
            int row = row0 + r;
            As[k * 193 + r] = (row < n) ? A[row * K + k0 + k] : 0.f;
        }
        __syncthreads();
#pragma unroll 8
        for (int k = 0; k < KC; k++) {
            const ull* b_ = (const ull*)&Bs[(k0 + k) * 96 + w * 8];
            ull bp0 = b_[0], bp1 = b_[1], bp2 = b_[2], bp3 = b_[3];
            const float* a_ = &As[k * 193 + lane];
#pragma unroll
            for (int f = 0; f < 6; f++) {
                float av = a_[f * 32];
                ull ap = pk2(av, av);
                acc[f][0] = fma2(ap, bp0, acc[f][0]);
                acc[f][1] = fma2(ap, bp1, acc[f][1]);
                acc[f][2] = fma2(ap, bp2, acc[f][2]);
                acc[f][3] = fma2(ap, bp3, acc[f][3]);
            }
        }
    }

#pragma unroll
    for (int f = 0; f < 6; f++) {
        int row = row0 + lane + f * 32;
        if (row < n) {
            float4 o0, o1;
            upk2(acc[f][0], o0.x, o0.y);
            upk2(acc[f][1], o0.z, o0.w);
            upk2(acc[f][2], o1.x, o1.y);
            upk2(acc[f][3], o1.z, o1.w);
            float* out = H + row * 96 + w * 8;
            *(float4*)(out) = o0;
            *(float4*)(out + 4) = o1;
        }
    }
}

// ================= alpha dot products (warp per node) =================
__global__ void k_alpha(const float* __restrict__ H, const float* __restrict__ asrc,
                        const float* __restrict__ adst, float* __restrict__ AS,
                        float* __restrict__ AD, int n) {
    int gtid = blockIdx.x * blockDim.x + threadIdx.x;
    int node = gtid >> 5, lane = gtid & 31;
    if (node >= n) return;
    float ps = 0.f, pd = 0.f;
    if (lane < 24) {
        float4 h4 = *(const float4*)(H + node * 96 + lane * 4);
        float4 s4 = *(const float4*)(asrc + lane * 4);
        float4 dd4 = *(const float4*)(adst + lane * 4);
        ps = h4.x * s4.x + h4.y * s4.y + h4.z * s4.z + h4.w * s4.w;
        pd = h4.x * dd4.x + h4.y * dd4.y + h4.z * dd4.z + h4.w * dd4.w;
    }
    float s = 0.f, d = 0.f;
#pragma unroll
    for (int j = 0; j < 6; j++) {
        int srcl = lane * 6 + j;
        s += __shfl_sync(0xffffffffu, ps, srcl & 31);
        d += __shfl_sync(0xffffffffu, pd, srcl & 31);
    }
    if (lane < 4) {
        AS[node * 4 + lane] = s;
        AD[node * 4 + lane] = d;
    }
}

// ================= softmax over incoming edges (warp per dst) =================
__global__ void k_softmax(const int* __restrict__ off, const int* __restrict__ srcs,
                          const float* __restrict__ AS, const float* __restrict__ AD,
                          float* __restrict__ W4, float* __restrict__ DEN, int n) {
    int gtid = blockIdx.x * blockDim.x + threadIdx.x;
    int node = gtid >> 5, lane = gtid & 31;
    if (node >= n) return;
    int beg = __ldg(&off[node]), end = __ldg(&off[node + 1]);
    float4 ad = *(const float4*)(AD + node * 4);

    float4 mx = make_float4(-INFINITY, -INFINITY, -INFINITY, -INFINITY);
    for (int e = beg + lane; e < end; e += 32) {
        int s = __ldg(&srcs[e]);
        float4 a = *(const float4*)(AS + s * 4);
        float4 v;
        v.x = a.x + ad.x; v.x = v.x > 0.f ? v.x : 0.2f * v.x; mx.x = fmaxf(mx.x, v.x);
        v.y = a.y + ad.y; v.y = v.y > 0.f ? v.y : 0.2f * v.y; mx.y = fmaxf(mx.y, v.y);
        v.z = a.z + ad.z; v.z = v.z > 0.f ? v.z : 0.2f * v.z; mx.z = fmaxf(mx.z, v.z);
        v.w = a.w + ad.w; v.w = v.w > 0.f ? v.w : 0.2f * v.w; mx.w = fmaxf(mx.w, v.w);
        *(float4*)(W4 + e * 4) = v;
    }
#pragma unroll
    for (int o = 16; o > 0; o >>= 1) {
        mx.x = fmaxf(mx.x, __shfl_xor_sync(0xffffffffu, mx.x, o));
        mx.y = fmaxf(mx.y, __shfl_xor_sync(0xffffffffu, mx.y, o));
        mx.z = fmaxf(mx.z, __shfl_xor_sync(0xffffffffu, mx.z, o));
        mx.w = fmaxf(mx.w, __shfl_xor_sync(0xffffffffu, mx.w, o));
    }

    float4 den = make_float4(0.f, 0.f, 0.f, 0.f);
    for (int e = beg + lane; e < end; e += 32) {
        float4 v = *(const float4*)(W4 + e * 4);
        float4 ex;
        ex.x = expf(v.x - mx.x);
        ex.y = expf(v.y - mx.y);
        ex.z = expf(v.z - mx.z);
        ex.w = expf(v.w - mx.w);
        *(float4*)(W4 + e * 4) = ex;
        den.x += ex.x; den.y += ex.y; den.z += ex.z; den.w += ex.w;
    }
#pragma unroll
    for (int o = 16; o > 0; o >>= 1) {
        den.x += __shfl_xor_sync(0xffffffffu, den.x, o);
        den.y += __shfl_xor_sync(0xffffffffu, den.y, o);
        den.z += __shfl_xor_sync(0xffffffffu, den.z, o);
        den.w += __shfl_xor_sync(0xffffffffu, den.w, o);
    }
    if (lane == 0) *(float4*)(DEN + node * 4) = den;
}

// ================= aggregation (warp per dst, prefetch-2) + bias + ELU =================
__global__ void k_agg(const int* __restrict__ off, const int* __restrict__ srcs,
                      const float* __restrict__ W4, const float* __restrict__ DEN,
                      const float* __restrict__ H, const float* __restrict__ bias,
                      float* __restrict__ OUT, int n) {
    int gtid = blockIdx.x * blockDim.x + threadIdx.x;
    int node = gtid >> 5, lane = gtid & 31;
    if (node >= n) return;
    int beg = __ldg(&off[node]), end = __ldg(&off[node + 1]);
    bool act = lane < 24;

    float4 acc = make_float4(0.f, 0.f, 0.f, 0.f);
    int sA = __ldg(&srcs[beg]);
    float4 wA = *(const float4*)(W4 + beg * 4);
    int sB = 0; float4 wB = wA;
    if (beg + 1 < end) { sB = __ldg(&srcs[beg + 1]); wB = *(const float4*)(W4 + (beg + 1) * 4); }

    for (int e = beg; e < end; e += 2) {
        int pA = 0, pB = 0; float4 qA = wA, qB = wB;
        if (e + 2 < end) { pA = __ldg(&srcs[e + 2]); qA = *(const float4*)(W4 + (e + 2) * 4); }
        if (e + 3 < end) { pB = __ldg(&srcs[e + 3]); qB = *(const float4*)(W4 + (e + 3) * 4); }
        if (act) {
            float wh = lane < 6 ? wA.x : (lane < 12 ? wA.y : (lane < 18 ? wA.z : wA.w));
            float4 h4 = *(const float4*)(H + sA * 96 + lane * 4);
            acc.x = fmaf(h4.x, wh, acc.x);
            acc.y = fmaf(h4.y, wh, acc.y);
            acc.z = fmaf(h4.z, wh, acc.z);
            acc.w = fmaf(h4.w, wh, acc.w);
        }
        if (e + 1 < end && act) {
            float wh = lane < 6 ? wB.x : (lane < 12 ? wB.y : (lane < 18 ? wB.z : wB.w));
            float4 h4 = *(const float4*)(H + sB * 96 + lane * 4);
            acc.x = fmaf(h4.x, wh, acc.x);
            acc.y = fmaf(h4.y, wh, acc.y);
            acc.z = fmaf(h4.z, wh, acc.z);
            acc.w = fmaf(h4.w, wh, acc.w);
        }
        sA = pA; wA = qA; sB = pB; wB = qB;
    }
    if (act) {
        float4 dv = *(const float4*)(DEN + node * 4);
        float dh = lane < 6 ? dv.x : (lane < 12 ? dv.y : (lane < 18 ? dv.z : dv.w));
        float inv = 1.f / (dh + 1e-16f);
        float4 b4 = *(const float4*)(bias + lane * 4);
        float4 o;
        o.x = acc.x * inv + b4.x;  o.x = o.x > 0.f ? o.x : expm1f(o.x);
        o.y = acc.y * inv + b4.y;  o.y = o.y > 0.f ? o.y : expm1f(o.y);
        o.z = acc.z * inv + b4.z;  o.z = o.z > 0.f ? o.z : expm1f(o.z);
        o.w = acc.w * inv + b4.w;  o.w = o.w > 0.f ? o.w : expm1f(o.w);
        *(float4*)(OUT + node * 96 + lane * 4) = o;
    }
}

// ================= gate MLP: smem weights, 2 nodes per warp =================
__global__ void k_gate(const float* __restrict__ H, const float* __restrict__ gw1,
                       const float* __restrict__ gb1, const float* __restrict__ gw2,
                       const float* __restrict__ gb2, const int* __restrict__ batch,
                       float* __restrict__ GATE, float* __restrict__ GM, int n) {
    __shared__ float sw1[96 * 48];
    __shared__ float sb1[48], sg2[48];
    int tid = threadIdx.x;
    for (int i = tid; i < 96 * 48; i += 256) sw1[i] = gw1[i];
    if (tid < 48) { sb1[tid] = gb1[tid]; sg2[tid] = gw2[tid]; }
    __syncthreads();
    int w = tid >> 5, lane = tid & 31;
    int base = blockIdx.x * 64;
    for (int it = 0; it < 4; it++) {
        int nodeA = base + it * 16 + w * 2;
        int nodeB = nodeA + 1;
        bool vA = nodeA < n, vB = nodeB < n;
        if (!vA) return;
        float a0 = 0.f, a1 = 0.f, b0 = 0.f, b1 = 0.f;
        const float* hA = H + nodeA * 96;
        const float* hB = H + nodeB * 96;
        for (int k = 0; k < 96; k++) {
            float w0 = sw1[k * 48 + lane];
            float hv0 = __ldg(&hA[k]);
            a0 = fmaf(hv0, w0, a0);
            float hv1 = vB ? __ldg(&hB[k]) : 0.f;
            b0 = fmaf(hv1, w0, b0);
            if (lane < 16) {
                float w1 = sw1[k * 48 + 32 + lane];
                a1 = fmaf(hv0, w1, a1);
                b1 = fmaf(hv1, w1, b1);
            }
        }
        float gA = fmaxf(a0 + sb1[lane], 0.f) * sg2[lane];
        float gB = fmaxf(b0 + sb1[lane], 0.f) * sg2[lane];
        if (lane < 16) {
            gA += fmaxf(a1 + sb1[32 + lane], 0.f) * sg2[32 + lane];
            gB += fmaxf(b1 + sb1[32 + lane], 0.f) * sg2[32 + lane];
        }
#pragma unroll
        for (int o = 16; o > 0; o >>= 1) {
            gA += __shfl_xor_sync(0xffffffffu, gA, o);
            gB += __shfl_xor_sync(0xffffffffu, gB, o);
        }
        if (lane == 0) {
            gA += gb2[0];
            GATE[nodeA] = gA;
            atomicMaxF(&GM[batch[nodeA]], gA);
        }
        if (lane == 1 && vB) {
            gB += gb2[0];
            GATE[nodeB] = gB;
            atomicMaxF(&GM[batch[nodeB]], gB);
        }
    }
}

__global__ void k_init_pool(float* __restrict__ GM, float* __restrict__ GDEN,
                            float* __restrict__ POOL) {
    int i = blockIdx.x * blockDim.x + threadIdx.x;
    if (i < GG) { GM[i] = -INFINITY; GDEN[i] = 0.f; }
    if (i < GG * 96) POOL[i] = 0.f;
}

__global__ void k_gate_exp(const float* __restrict__ GATE, const float* __restrict__ GM,
                           const int* __restrict__ batch, float* __restrict__ GE,
                           float* __restrict__ GDEN, int n) {
    __shared__ float sden[GG];
    for (int i = threadIdx.x; i < GG; i += blockDim.x) sden[i] = 0.f;
    __syncthreads();
    int i = blockIdx.x * blockDim.x + threadIdx.x;
    if (i < n) {
        int b = batch[i];
        float m = GM[b];
        if (m == -INFINITY) m = 0.f;
        float e = expf(GATE[i] - m);
        GE[i] = e;
        atomicAdd(&sden[b], e);
    }
    __syncthreads();
    for (int i2 = threadIdx.x; i2 < GG; i2 += blockDim.x)
        if (sden[i2] != 0.f) atomicAdd(&GDEN[i2], sden[i2]);
}

// ================= pooling: 8 blocks per graph, atomic merge =================
__global__ void k_pool2(const float* __restrict__ H, const float* __restrict__ GE,
                        const float* __restrict__ GDEN, const int* __restrict__ batch,
                        float* __restrict__ POOL, int n) {
    __shared__ float red[192];
    int g = blockIdx.x;
    int part = blockIdx.y;           // 0..7
    int tid = threadIdx.x;           // 192 threads
    int lo = 0, hi = n;
    while (lo < hi) { int mid = (lo + hi) >> 1; if (__ldg(&batch[mid]) < g) lo = mid + 1; else hi = mid; }
    int beg = lo;
    lo = beg; hi = n;
    while (lo < hi) { int mid = (lo + hi) >> 1; if (__ldg(&batch[mid]) < g + 1) lo = mid + 1; else hi = mid; }
    int end = lo;

    float invden = 1.f / (GDEN[g] + 1e-16f);
    int half = tid / 96, c = tid - half * 96;
    float acc = 0.f;
    for (int node = beg + part * 2 + half; node < end; node += 16) {
        float wv = __ldg(&GE[node]) * invden;
        acc = fmaf(__ldg(&H[node * 96 + c]), wv, acc);
    }
    red[tid] = acc;
    __syncthreads();
    if (tid < 96) {
        float v = red[tid] + red[tid + 96];
        atomicAdd(&POOL[g * 96 + tid], v);
    }
}

__global__ void k_final(const float* __restrict__ POOL, const float* __restrict__ fw1,
                        const float* __restrict__ fb1, const float* __restrict__ fw2,
                        const float* __restrict__ fb2, float* __restrict__ out) {
    __shared__ float pr[96];
    __shared__ float hid[96];
    int g = blockIdx.x, j = threadIdx.x;
    pr[j] = POOL[g * 96 + j];
    __syncthreads();
    float a = fb1[j];
#pragma unroll 8
    for (int k = 0; k < 96; k++) a += pr[k] * fw1[k * 96 + j];
    hid[j] = fmaxf(a, 0.f);
    __syncthreads();
    if (j < 3) {
        float o = fb2[j];
        for (int k = 0; k < 96; k++) o += hid[k] * fw2[k * 3 + j];
        out[g * 3 + j] = o;
    }
}

// ================= host =================
extern "C" void kernel_launch(void* const* d_in, const int* in_sizes, int n_in,
                              void* d_out, int out_size) {
    const float* x     = (const float*)d_in[0];
    const int*   ei    = (const int*)d_in[1];
    const int*   batch = (const int*)d_in[2];
    int idx = 3;
    if (n_in > 3 && in_sizes[3] == 1) idx = 4;
    const float* W1  = (const float*)d_in[idx++];
    const float* as1 = (const float*)d_in[idx++];
    const float* ad1 = (const float*)d_in[idx++];
    const float* b1  = (const float*)d_in[idx++];
    const float* W2  = (const float*)d_in[idx++];
    const float* as2 = (const float*)d_in[idx++];
    const float* ad2 = (const float*)d_in[idx++];
    const float* b2  = (const float*)d_in[idx++];
    const float* gw1 = (const float*)d_in[idx++];
    const float* gb1 = (const float*)d_in[idx++];
    const float* gw2 = (const float*)d_in[idx++];
    const float* gb2 = (const float*)d_in[idx++];
    const float* fw1 = (const float*)d_in[idx++];
    const float* fb1 = (const float*)d_in[idx++];
    const float* fw2 = (const float*)d_in[idx++];
    const float* fb2 = (const float*)d_in[idx++];

    int n    = in_sizes[0] / 128;
    int eraw = in_sizes[1] / 2;
    int etot = eraw + n;

    float *h, *o, *as_, *ad_, *den, *w4, *gate, *ge, *gm, *gden, *pool;
    int *deg, *part, *bsum, *off, *srcs;
    cudaGetSymbolAddress((void**)&h,    d_h);
    cudaGetSymbolAddress((void**)&o,    d_o);
    cudaGetSymbolAddress((void**)&as_,  d_as);
    cudaGetSymbolAddress((void**)&ad_,  d_ad);
    cudaGetSymbolAddress((void**)&den,  d_den);
    cudaGetSymbolAddress((void**)&w4,   d_w);
    cudaGetSymbolAddress((void**)&gate, d_gate);
    cudaGetSymbolAddress((void**)&ge,   d_ge);
    cudaGetSymbolAddress((void**)&gm,   d_gm);
    cudaGetSymbolAddress((void**)&gden, d_gden);
    cudaGetSymbolAddress((void**)&pool, d_pool);
    cudaGetSymbolAddress((void**)&deg,  d_deg);
    cudaGetSymbolAddress((void**)&part, d_part);
    cudaGetSymbolAddress((void**)&bsum, d_bsum);
    cudaGetSymbolAddress((void**)&off,  d_off);
    cudaGetSymbolAddress((void**)&srcs, d_srcs);

    int smem1 = (128 * 96 + 64 * 193) * 4;   // 98560 B
    int smem2 = (96 * 96 + 96 * 193) * 4;    // 110976 B
    cudaFuncSetAttribute(k_gemm2<128, 64>, cudaFuncAttributeMaxDynamicSharedMemorySize, smem1);
    cudaFuncSetAttribute(k_gemm2<96, 96>,  cudaFuncAttributeMaxDynamicSharedMemorySize, smem2);

    int gEdge  = (etot + 255) / 256;
    int gWarp  = (n * 32 + 255) / 256;
    int gGemm  = (n + 191) / 192;
    int gNode  = (n + 255) / 256;
    int gScan  = (n + 1023) / 1024;

    // ---- CSR build ----
    cudaMemsetAsync(deg, 0, n * sizeof(int));
    k_hist<<<gEdge, 256>>>(ei, deg, etot, eraw);
    k_scanA<<<gScan, 1024>>>(deg, part, bsum, n);
    k_scanB<<<1, 32>>>(bsum, gScan);
    k_scanC<<<gScan, 1024>>>(part, bsum, off, deg, n, etot);
    k_scatter<<<gEdge, 256>>>(ei, deg, srcs, etot, eraw);

    // ---- layer 1 ----
    k_gemm2<128, 64><<<gGemm, 384, smem1>>>(x, W1, h, n);
    k_alpha<<<gWarp, 256>>>(h, as1, ad1, as_, ad_, n);
    k_softmax<<<gWarp, 256>>>(off, srcs, as_, ad_, w4, den, n);
    k_agg<<<gWarp, 256>>>(off, srcs, w4, den, h, b1, o, n);

    // ---- layer 2 ----
    k_gemm2<96, 96><<<gGemm, 384, smem2>>>(o, W2, h, n);
    k_alpha<<<gWarp, 256>>>(h, as2, ad2, as_, ad_, n);
    k_softmax<<<gWarp, 256>>>(off, srcs, as_, ad_, w4, den, n);
    k_agg<<<gWarp, 256>>>(off, srcs, w4, den, h, b2, o, n);

    // ---- global attention pool + final MLP ----
    k_init_pool<<<24, 256>>>(gm, gden, pool);
    k_gate<<<(n + 63) / 64, 256>>>(o, gw1, gb1, gw2, gb2, batch, gate, gm, n);
    k_gate_exp<<<gNode, 256>>>(gate, gm, batch, ge, gden, n);
    k_pool2<<<dim3(GG, 8), 192>>>(o, ge, gden, batch, pool, n);
    k_final<<<GG, 96>>>(pool, fw1, fb1, fw2, fb2, (float*)d_out);
}

// round 6
// speedup vs baseline: 1.9882x; 1.1657x over previous
#include <cuda_runtime.h>
#include <math.h>

#define NN 50000
#define EE 800000
#define ETOT (EE + NN)
#define GG 64

// ---------------- scratch ----------------
__device__ float d_h[NN * 96];
__device__ float d_o[NN * 96];
__device__ float d_as[NN * 4];
__device__ float d_ad[NN * 4];
__device__ int   d_deg[NN];
__device__ int   d_part[NN];
__device__ int   d_bsum[64];
__device__ int   d_off[NN + 1];
__device__ int   d_srcs[ETOT];
__device__ float d_gate[NN];
__device__ float d_ge[NN];
__device__ float d_gm[GG];
__device__ float d_gden[GG];
__device__ float d_pool[GG * 96];

__device__ __forceinline__ void atomicMaxF(float* a, float v) {
    if (v >= 0.f) atomicMax((int*)a, __float_as_int(v));
    else          atomicMin((unsigned int*)a, __float_as_uint(v));
}

typedef unsigned long long ull;
__device__ __forceinline__ ull pk2(float x, float y) {
    ull r;
    asm("mov.b64 %0, {%1, %2};" : "=l"(r) : "f"(x), "f"(y));
    return r;
}
__device__ __forceinline__ ull fma2(ull a, ull b, ull c) {
    ull d;
    asm("fma.rn.f32x2 %0, %1, %2, %3;" : "=l"(d) : "l"(a), "l"(b), "l"(c));
    return d;
}
__device__ __forceinline__ void upk2(ull v, float& x, float& y) {
    asm("mov.b64 {%0, %1}, %2;" : "=f"(x), "=f"(y) : "l"(v));
}

// ================= CSR build =================
__global__ void k_hist(const int* __restrict__ ei, int* __restrict__ deg, int etot, int eraw) {
    int e = blockIdx.x * blockDim.x + threadIdx.x;
    if (e >= etot) return;
    int d = (e < eraw) ? __ldg(&ei[eraw + e]) : e - eraw;
    atomicAdd(&deg[d], 1);
}

__global__ void k_scanA(const int* __restrict__ deg, int* __restrict__ part,
                        int* __restrict__ bsum, int n) {
    __shared__ int wsum[32];
    int t = threadIdx.x;
    int i = blockIdx.x * 1024 + t;
    int v = (i < n) ? deg[i] : 0;
    int lane = t & 31, w = t >> 5;
    int x = v;
#pragma unroll
    for (int o = 1; o < 32; o <<= 1) {
        int y = __shfl_up_sync(0xffffffffu, x, o);
        if (lane >= o) x += y;
    }
    if (lane == 31) wsum[w] = x;
    __syncthreads();
    if (w == 0) {
        int s = wsum[lane];
#pragma unroll
        for (int o = 1; o < 32; o <<= 1) {
            int y = __shfl_up_sync(0xffffffffu, s, o);
            if (lane >= o) s += y;
        }
        wsum[lane] = s;
    }
    __syncthreads();
    int woff = (w > 0) ? wsum[w - 1] : 0;
    if (i < n) part[i] = x - v + woff;
    if (t == 0) bsum[blockIdx.x] = wsum[31];
}

// stage B: parallel exclusive scan of up to 64 block totals
__global__ void k_scanB(int* __restrict__ bsum, int nb) {
    __shared__ int w0tot;
    int t = threadIdx.x;              // 64 threads
    int lane = t & 31, w = t >> 5;
    int v = (t < nb) ? bsum[t] : 0;
    int x = v;
#pragma unroll
    for (int o = 1; o < 32; o <<= 1) {
        int y = __shfl_up_sync(0xffffffffu, x, o);
        if (lane >= o) x += y;
    }
    if (w == 0 && lane == 31) w0tot = x;
    __syncthreads();
    if (w == 1) x += w0tot;
    if (t < nb) bsum[t] = x - v;      // exclusive
}

__global__ void k_scanC(const int* __restrict__ part, const int* __restrict__ bsum,
                        int* __restrict__ off, int* __restrict__ cur, int n, int etot) {
    int i = blockIdx.x * 1024 + threadIdx.x;
    if (i < n) {
        int v = part[i] + bsum[blockIdx.x];
        off[i] = v;
        cur[i] = v;
    }
    if (i == 0) off[n] = etot;
}

__global__ void k_scatter(const int* __restrict__ ei, int* __restrict__ cur,
                          int* __restrict__ srcs, int etot, int eraw) {
    int e = blockIdx.x * blockDim.x + threadIdx.x;
    if (e >= etot) return;
    int s, d;
    if (e < eraw) { s = __ldg(&ei[e]); d = __ldg(&ei[eraw + e]); }
    else          { s = d = e - eraw; }
    int pos = atomicAdd(&cur[d], 1);
    srcs[pos] = s;
}

// ================= GEMM + fused alpha epilogue =================
// C[n,96] = A[n,K] @ W[K,96]; TM=192, 384 thr, 2 blocks/SM.
// warp w owns cols [w*8,w*8+8) — entirely inside head w/3 (24 = 3*8).
// Alpha dots reduced via smem atomics into the (reused) dynamic smem.
template<int K, int KC>
__global__ void __launch_bounds__(384, 2) k_gemm2(const float* __restrict__ A,
                                                  const float* __restrict__ W,
                                                  const float* __restrict__ asrc,
                                                  const float* __restrict__ adst,
                                                  float* __restrict__ H,
                                                  float* __restrict__ AS,
                                                  float* __restrict__ AD, int n) {
    extern __shared__ float sm[];
    float* Bs = sm;              // K*96 (full weights, global-k)
    float* As = sm + K * 96;     // KC*193
    int tid = threadIdx.x;
    int w = tid >> 5, lane = tid & 31;
    int row0 = blockIdx.x * 192;
    int head = w / 3;

    ull acc[6][4];
#pragma unroll
    for (int f = 0; f < 6; f++)
#pragma unroll
        for (int j = 0; j < 4; j++) acc[f][j] = 0ull;

    for (int i = tid; i < K * 96; i += 384) Bs[i] = W[i];

    for (int k0 = 0; k0 < K; k0 += KC) {
        __syncthreads();
        for (int i = tid; i < 192 * KC; i += 384) {
            int k = i % KC, r = i / KC;
            int row = row0 + r;
            As[k * 193 + r] = (row < n) ? A[row * K + k0 + k] : 0.f;
        }
        __syncthreads();
#pragma unroll 8
        for (int k = 0; k < KC; k++) {
            const ull* b_ = (const ull*)&Bs[(k0 + k) * 96 + w * 8];
            ull bp0 = b_[0], bp1 = b_[1], bp2 = b_[2], bp3 = b_[3];
            const float* a_ = &As[k * 193 + lane];
#pragma unroll
            for (int f = 0; f < 6; f++) {
                float av = a_[f * 32];
                ull ap = pk2(av, av);
                acc[f][0] = fma2(ap, bp0, acc[f][0]);
                acc[f][1] = fma2(ap, bp1, acc[f][1]);
                acc[f][2] = fma2(ap, bp2, acc[f][2]);
                acc[f][3] = fma2(ap, bp3, acc[f][3]);
            }
        }
    }

    // ---- epilogue: write H + alpha partial reduction into reused smem ----
    float a_s[8], a_d[8];
#pragma unroll
    for (int j = 0; j < 8; j++) {
        a_s[j] = __ldg(&asrc[w * 8 + j]);
        a_d[j] = __ldg(&adst[w * 8 + j]);
    }
    float* sAl = sm;                  // 192 rows * 8 (4 AS + 4 AD) = 1536 floats
    __syncthreads();                  // everyone done reading Bs/As
    for (int i = tid; i < 192 * 8; i += 384) sAl[i] = 0.f;
    __syncthreads();

#pragma unroll
    for (int f = 0; f < 6; f++) {
        int r = lane + f * 32;
        int row = row0 + r;
        float o0x, o0y, o0z, o0w, o1x, o1y, o1z, o1w;
        upk2(acc[f][0], o0x, o0y);
        upk2(acc[f][1], o0z, o0w);
        upk2(acc[f][2], o1x, o1y);
        upk2(acc[f][3], o1z, o1w);
        if (row < n) {
            float* out = H + row * 96 + w * 8;
            *(float4*)(out)     = make_float4(o0x, o0y, o0z, o0w);
            *(float4*)(out + 4) = make_float4(o1x, o1y, o1z, o1w);
        }
        float sp = o0x * a_s[0] + o0y * a_s[1] + o0z * a_s[2] + o0w * a_s[3]
                 + o1x * a_s[4] + o1y * a_s[5] + o1z * a_s[6] + o1w * a_s[7];
        float dp = o0x * a_d[0] + o0y * a_d[1] + o0z * a_d[2] + o0w * a_d[3]
                 + o1x * a_d[4] + o1y * a_d[5] + o1z * a_d[6] + o1w * a_d[7];
        atomicAdd(&sAl[r * 8 + head], sp);
        atomicAdd(&sAl[r * 8 + 4 + head], dp);
    }
    __syncthreads();
    for (int i = tid; i < 192 * 4; i += 384) {
        int r = i >> 2, hh = i & 3;
        int row = row0 + r;
        if (row < n) {
            AS[row * 4 + hh] = sAl[r * 8 + hh];
            AD[row * 4 + hh] = sAl[r * 8 + 4 + hh];
        }
    }
}

// ================= fused softmax + aggregation (warp per dst) =================
__global__ void k_sagg(const int* __restrict__ off, const int* __restrict__ srcs,
                       const float* __restrict__ AS, const float* __restrict__ AD,
                       const float* __restrict__ H, const float* __restrict__ bias,
                       float* __restrict__ OUT, int n) {
    __shared__ int   ssrc[8][32];
    __shared__ float sex[8][128];
    int gtid = blockIdx.x * blockDim.x + threadIdx.x;
    int node = gtid >> 5, lane = gtid & 31;
    int ws = threadIdx.x >> 5;
    if (node >= n) return;
    int beg = __ldg(&off[node]), end = __ldg(&off[node + 1]);
    float4 ad = *(const float4*)(AD + node * 4);

    // pass 1: per-head max
    float4 mx = make_float4(-INFINITY, -INFINITY, -INFINITY, -INFINITY);
    for (int e = beg + lane; e < end; e += 32) {
        int s = __ldg(&srcs[e]);
        float4 a = *(const float4*)(AS + s * 4);
        float v;
        v = a.x + ad.x; v = v > 0.f ? v : 0.2f * v; mx.x = fmaxf(mx.x, v);
        v = a.y + ad.y; v = v > 0.f ? v : 0.2f * v; mx.y = fmaxf(mx.y, v);
        v = a.z + ad.z; v = v > 0.f ? v : 0.2f * v; mx.z = fmaxf(mx.z, v);
        v = a.w + ad.w; v = v > 0.f ? v : 0.2f * v; mx.w = fmaxf(mx.w, v);
    }
#pragma unroll
    for (int o = 16; o > 0; o >>= 1) {
        mx.x = fmaxf(mx.x, __shfl_xor_sync(0xffffffffu, mx.x, o));
        mx.y = fmaxf(mx.y, __shfl_xor_sync(0xffffffffu, mx.y, o));
        mx.z = fmaxf(mx.z, __shfl_xor_sync(0xffffffffu, mx.z, o));
        mx.w = fmaxf(mx.w, __shfl_xor_sync(0xffffffffu, mx.w, o));
    }

    // pass 2: chunks of 32 edges — exp into smem, then immediate aggregation
    bool act = lane < 24;
    int head = lane / 6;                 // head of this lane's 4 channels (lane<24)
    float4 acc = make_float4(0.f, 0.f, 0.f, 0.f);
    float4 den = make_float4(0.f, 0.f, 0.f, 0.f);
    for (int c0 = beg; c0 < end; c0 += 32) {
        int e = c0 + lane;
        if (e < end) {
            int s = __ldg(&srcs[e]);
            float4 a = *(const float4*)(AS + s * 4);
            float v; float4 ex;
            v = a.x + ad.x; v = v > 0.f ? v : 0.2f * v; ex.x = expf(v - mx.x);
            v = a.y + ad.y; v = v > 0.f ? v : 0.2f * v; ex.y = expf(v - mx.y);
            v = a.z + ad.z; v = v > 0.f ? v : 0.2f * v; ex.z = expf(v - mx.z);
            v = a.w + ad.w; v = v > 0.f ? v : 0.2f * v; ex.w = expf(v - mx.w);
            den.x += ex.x; den.y += ex.y; den.z += ex.z; den.w += ex.w;
            ssrc[ws][lane] = s;
            *(float4*)&sex[ws][lane * 4] = ex;
        }
        __syncwarp();
        int cnt = min(32, end - c0);
        if (act) {
            for (int j = 0; j < cnt; j++) {
                int s = ssrc[ws][j];
                float wv = sex[ws][j * 4 + head];
                float4 h4 = *(const float4*)(H + s * 96 + lane * 4);
                acc.x = fmaf(h4.x, wv, acc.x);
                acc.y = fmaf(h4.y, wv, acc.y);
                acc.z = fmaf(h4.z, wv, acc.z);
                acc.w = fmaf(h4.w, wv, acc.w);
            }
        }
        __syncwarp();
    }
#pragma unroll
    for (int o = 16; o > 0; o >>= 1) {
        den.x += __shfl_xor_sync(0xffffffffu, den.x, o);
        den.y += __shfl_xor_sync(0xffffffffu, den.y, o);
        den.z += __shfl_xor_sync(0xffffffffu, den.z, o);
        den.w += __shfl_xor_sync(0xffffffffu, den.w, o);
    }
    if (act) {
        float dh = head == 0 ? den.x : (head == 1 ? den.y : (head == 2 ? den.z : den.w));
        float inv = 1.f / (dh + 1e-16f);
        float4 b4 = *(const float4*)(bias + lane * 4);
        float4 o;
        o.x = acc.x * inv + b4.x;  o.x = o.x > 0.f ? o.x : expm1f(o.x);
        o.y = acc.y * inv + b4.y;  o.y = o.y > 0.f ? o.y : expm1f(o.y);
        o.z = acc.z * inv + b4.z;  o.z = o.z > 0.f ? o.z : expm1f(o.z);
        o.w = acc.w * inv + b4.w;  o.w = o.w > 0.f ? o.w : expm1f(o.w);
        *(float4*)(OUT + node * 96 + lane * 4) = o;
    }
}

// ================= gate MLP: smem weights, 2 nodes per warp =================
__global__ void k_gate(const float* __restrict__ H, const float* __restrict__ gw1,
                       const float* __restrict__ gb1, const float* __restrict__ gw2,
                       const float* __restrict__ gb2, const int* __restrict__ batch,
                       float* __restrict__ GATE, float* __restrict__ GM, int n) {
    __shared__ float sw1[96 * 48];
    __shared__ float sb1[48], sg2[48];
    int tid = threadIdx.x;
    for (int i = tid; i < 96 * 48; i += 256) sw1[i] = gw1[i];
    if (tid < 48) { sb1[tid] = gb1[tid]; sg2[tid] = gw2[tid]; }
    __syncthreads();
    int w = tid >> 5, lane = tid & 31;
    int base = blockIdx.x * 64;
    for (int it = 0; it < 4; it++) {
        int nodeA = base + it * 16 + w * 2;
        int nodeB = nodeA + 1;
        bool vA = nodeA < n, vB = nodeB < n;
        if (!vA) return;
        float a0 = 0.f, a1 = 0.f, b0 = 0.f, b1 = 0.f;
        const float* hA = H + nodeA * 96;
        const float* hB = H + nodeB * 96;
        for (int k = 0; k < 96; k++) {
            float w0 = sw1[k * 48 + lane];
            float hv0 = __ldg(&hA[k]);
            a0 = fmaf(hv0, w0, a0);
            float hv1 = vB ? __ldg(&hB[k]) : 0.f;
            b0 = fmaf(hv1, w0, b0);
            if (lane < 16) {
                float w1 = sw1[k * 48 + 32 + lane];
                a1 = fmaf(hv0, w1, a1);
                b1 = fmaf(hv1, w1, b1);
            }
        }
        float gA = fmaxf(a0 + sb1[lane], 0.f) * sg2[lane];
        float gB = fmaxf(b0 + sb1[lane], 0.f) * sg2[lane];
        if (lane < 16) {
            gA += fmaxf(a1 + sb1[32 + lane], 0.f) * sg2[32 + lane];
            gB += fmaxf(b1 + sb1[32 + lane], 0.f) * sg2[32 + lane];
        }
#pragma unroll
        for (int o = 16; o > 0; o >>= 1) {
            gA += __shfl_xor_sync(0xffffffffu, gA, o);
            gB += __shfl_xor_sync(0xffffffffu, gB, o);
        }
        if (lane == 0) {
            gA += gb2[0];
            GATE[nodeA] = gA;
            atomicMaxF(&GM[batch[nodeA]], gA);
        }
        if (lane == 1 && vB) {
            gB += gb2[0];
            GATE[nodeB] = gB;
            atomicMaxF(&GM[batch[nodeB]], gB);
        }
    }
}

__global__ void k_init_pool(float* __restrict__ GM, float* __restrict__ GDEN,
                            float* __restrict__ POOL) {
    int i = blockIdx.x * blockDim.x + threadIdx.x;
    if (i < GG) { GM[i] = -INFINITY; GDEN[i] = 0.f; }
    if (i < GG * 96) POOL[i] = 0.f;
}

__global__ void k_gate_exp(const float* __restrict__ GATE, const float* __restrict__ GM,
                           const int* __restrict__ batch, float* __restrict__ GE,
                           float* __restrict__ GDEN, int n) {
    __shared__ float sden[GG];
    for (int i = threadIdx.x; i < GG; i += blockDim.x) sden[i] = 0.f;
    __syncthreads();
    int i = blockIdx.x * blockDim.x + threadIdx.x;
    if (i < n) {
        int b = batch[i];
        float m = GM[b];
        if (m == -INFINITY) m = 0.f;
        float e = expf(GATE[i] - m);
        GE[i] = e;
        atomicAdd(&sden[b], e);
    }
    __syncthreads();
    for (int i2 = threadIdx.x; i2 < GG; i2 += blockDim.x)
        if (sden[i2] != 0.f) atomicAdd(&GDEN[i2], sden[i2]);
}

// ================= pooling: 8 blocks per graph, atomic merge =================
__global__ void k_pool2(const float* __restrict__ H, const float* __restrict__ GE,
                        const float* __restrict__ GDEN, const int* __restrict__ batch,
                        float* __restrict__ POOL, int n) {
    __shared__ float red[192];
    int g = blockIdx.x;
    int part = blockIdx.y;
    int tid = threadIdx.x;
    int lo = 0, hi = n;
    while (lo < hi) { int mid = (lo + hi) >> 1; if (__ldg(&batch[mid]) < g) lo = mid + 1; else hi = mid; }
    int beg = lo;
    lo = beg; hi = n;
    while (lo < hi) { int mid = (lo + hi) >> 1; if (__ldg(&batch[mid]) < g + 1) lo = mid + 1; else hi = mid; }
    int end = lo;

    float invden = 1.f / (GDEN[g] + 1e-16f);
    int half = tid / 96, c = tid - half * 96;
    float acc = 0.f;
    for (int node = beg + part * 2 + half; node < end; node += 16) {
        float wv = __ldg(&GE[node]) * invden;
        acc = fmaf(__ldg(&H[node * 96 + c]), wv, acc);
    }
    red[tid] = acc;
    __syncthreads();
    if (tid < 96) {
        float v = red[tid] + red[tid + 96];
        atomicAdd(&POOL[g * 96 + tid], v);
    }
}

__global__ void k_final(const float* __restrict__ POOL, const float* __restrict__ fw1,
                        const float* __restrict__ fb1, const float* __restrict__ fw2,
                        const float* __restrict__ fb2, float* __restrict__ out) {
    __shared__ float pr[96];
    __shared__ float hid[96];
    int g = blockIdx.x, j = threadIdx.x;
    pr[j] = POOL[g * 96 + j];
    __syncthreads();
    float a = fb1[j];
#pragma unroll 8
    for (int k = 0; k < 96; k++) a += pr[k] * fw1[k * 96 + j];
    hid[j] = fmaxf(a, 0.f);
    __syncthreads();
    if (j < 3) {
        float o = fb2[j];
        for (int k = 0; k < 96; k++) o += hid[k] * fw2[k * 3 + j];
        out[g * 3 + j] = o;
    }
}

// ================= host =================
extern "C" void kernel_launch(void* const* d_in, const int* in_sizes, int n_in,
                              void* d_out, int out_size) {
    const float* x     = (const float*)d_in[0];
    const int*   ei    = (const int*)d_in[1];
    const int*   batch = (const int*)d_in[2];
    int idx = 3;
    if (n_in > 3 && in_sizes[3] == 1) idx = 4;
    const float* W1  = (const float*)d_in[idx++];
    const float* as1 = (const float*)d_in[idx++];
    const float* ad1 = (const float*)d_in[idx++];
    const float* b1  = (const float*)d_in[idx++];
    const float* W2  = (const float*)d_in[idx++];
    const float* as2 = (const float*)d_in[idx++];
    const float* ad2 = (const float*)d_in[idx++];
    const float* b2  = (const float*)d_in[idx++];
    const float* gw1 = (const float*)d_in[idx++];
    const float* gb1 = (const float*)d_in[idx++];
    const float* gw2 = (const float*)d_in[idx++];
    const float* gb2 = (const float*)d_in[idx++];
    const float* fw1 = (const float*)d_in[idx++];
    const float* fb1 = (const float*)d_in[idx++];
    const float* fw2 = (const float*)d_in[idx++];
    const float* fb2 = (const float*)d_in[idx++];

    int n    = in_sizes[0] / 128;
    int eraw = in_sizes[1] / 2;
    int etot = eraw + n;

    float *h, *o, *as_, *ad_, *gate, *ge, *gm, *gden, *pool;
    int *deg, *part, *bsum, *off, *srcs;
    cudaGetSymbolAddress((void**)&h,    d_h);
    cudaGetSymbolAddress((void**)&o,    d_o);
    cudaGetSymbolAddress((void**)&as_,  d_as);
    cudaGetSymbolAddress((void**)&ad_,  d_ad);
    cudaGetSymbolAddress((void**)&gate, d_gate);
    cudaGetSymbolAddress((void**)&ge,   d_ge);
    cudaGetSymbolAddress((void**)&gm,   d_gm);
    cudaGetSymbolAddress((void**)&gden, d_gden);
    cudaGetSymbolAddress((void**)&pool, d_pool);
    cudaGetSymbolAddress((void**)&deg,  d_deg);
    cudaGetSymbolAddress((void**)&part, d_part);
    cudaGetSymbolAddress((void**)&bsum, d_bsum);
    cudaGetSymbolAddress((void**)&off,  d_off);
    cudaGetSymbolAddress((void**)&srcs, d_srcs);

    int smem1 = (128 * 96 + 64 * 193) * 4;   // 98560 B
    int smem2 = (96 * 96 + 96 * 193) * 4;    // 110976 B
    cudaFuncSetAttribute(k_gemm2<128, 64>, cudaFuncAttributeMaxDynamicSharedMemorySize, smem1);
    cudaFuncSetAttribute(k_gemm2<96, 96>,  cudaFuncAttributeMaxDynamicSharedMemorySize, smem2);

    int gEdge  = (etot + 255) / 256;
    int gWarp  = (n * 32 + 255) / 256;
    int gGemm  = (n + 191) / 192;
    int gNode  = (n + 255) / 256;
    int gScan  = (n + 1023) / 1024;

    // ---- CSR build ----
    cudaMemsetAsync(deg, 0, n * sizeof(int));
    k_hist<<<gEdge, 256>>>(ei, deg, etot, eraw);
    k_scanA<<<gScan, 1024>>>(deg, part, bsum, n);
    k_scanB<<<1, 64>>>(bsum, gScan);
    k_scanC<<<gScan, 1024>>>(part, bsum, off, deg, n, etot);
    k_scatter<<<gEdge, 256>>>(ei, deg, srcs, etot, eraw);

    // ---- layer 1 ----
    k_gemm2<128, 64><<<gGemm, 384, smem1>>>(x, W1, as1, ad1, h, as_, ad_, n);
    k_sagg<<<gWarp, 256>>>(off, srcs, as_, ad_, h, b1, o, n);

    // ---- layer 2 ----
    k_gemm2<96, 96><<<gGemm, 384, smem2>>>(o, W2, as2, ad2, h, as_, ad_, n);
    k_sagg<<<gWarp, 256>>>(off, srcs, as_, ad_, h, b2, o, n);

    // ---- global attention pool + final MLP ----
    k_init_pool<<<24, 256>>>(gm, gden, pool);
    k_gate<<<(n + 63) / 64, 256>>>(o, gw1, gb1, gw2, gb2, batch, gate, gm, n);
    k_gate_exp<<<gNode, 256>>>(gate, gm, batch, ge, gden, n);
    k_pool2<<<dim3(GG, 8), 192>>>(o, ge, gden, batch, pool, n);
    k_final<<<GG, 96>>>(pool, fw1, fb1, fw2, fb2, (float*)d_out);
}